// round 1
// baseline (speedup 1.0000x reference)
#include <cuda_runtime.h>
#include <cstdint>
#include <math.h>

// ---------------------------------------------------------------------------
// Problem constants (fixed shapes from the reference)
// ---------------------------------------------------------------------------
namespace {
constexpr int B_   = 2;
constexpr int S_   = 2048;
constexpr int D_   = 2048;
constexpr int H_   = 16;
constexpr int HKV_ = 4;
constexpr int G_   = H_ / HKV_;   // 4
constexpr int RQ_  = 1024;
constexpr int RKV_ = 512;
constexpr int DH_  = 192;
constexpr int DR_  = 64;
constexpr int DN_  = 128;
constexpr int DV_  = 128;
constexpr int M_   = B_ * S_;     // 4096 rows
}

// ---------------------------------------------------------------------------
// Scratch buffers (static device globals; no runtime allocation)
// ---------------------------------------------------------------------------
__device__ float g_qa  [(size_t)M_ * RQ_];                 // 16 MB
__device__ float g_qn  [(size_t)M_ * RQ_];                 // 16 MB
__device__ float g_qb  [(size_t)M_ * H_ * DH_];            // 48 MB
__device__ float g_kva [(size_t)M_ * (RKV_ + DR_)];        // 9 MB
__device__ float g_kvn [(size_t)M_ * RKV_];                // 8 MB
__device__ float g_kvb [(size_t)M_ * HKV_ * (DN_ + DV_)];  // 16 MB
__device__ float g_Q   [(size_t)B_ * H_   * S_ * DH_];     // 50 MB
__device__ float g_K   [(size_t)B_ * HKV_ * S_ * DH_];     // 12.6 MB
__device__ float g_V   [(size_t)B_ * HKV_ * S_ * DV_];     // 8.4 MB
__device__ float g_attn[(size_t)M_ * H_ * DV_];            // 33.5 MB

// ---------------------------------------------------------------------------
// Generic tiled SGEMM with bias: C[M,N] = A[M,K] @ W[K,N] + bias[N]
// All M,N,K used here are multiples of 64/64/16 -> no bounds checks.
// ---------------------------------------------------------------------------
__global__ void sgemm_bias(const float* __restrict__ A, const float* __restrict__ W,
                           const float* __restrict__ bias, float* __restrict__ C,
                           int M, int N, int K) {
    constexpr int BM = 64, BN = 64, BK = 16;
    __shared__ float As[BK][BM + 1];
    __shared__ float Ws[BK][BN];
    const int tid = threadIdx.x;          // 256 threads
    const int tx  = tid & 15;
    const int ty  = tid >> 4;
    const int row0 = blockIdx.y * BM;
    const int col0 = blockIdx.x * BN;

    float acc[4][4] = {};

    for (int k0 = 0; k0 < K; k0 += BK) {
        // load A tile: coalesced along K (16 consecutive floats per 16 lanes)
        #pragma unroll
        for (int it = 0; it < 4; ++it) {
            int i  = tid + it * 256;
            int kk = i & 15;
            int mm = i >> 4;
            As[kk][mm] = A[(size_t)(row0 + mm) * K + (k0 + kk)];
        }
        // load W tile: coalesced along N
        #pragma unroll
        for (int it = 0; it < 4; ++it) {
            int i  = tid + it * 256;
            int nn = i & 63;
            int kk = i >> 6;
            Ws[kk][nn] = W[(size_t)(k0 + kk) * N + (col0 + nn)];
        }
        __syncthreads();
        #pragma unroll
        for (int kk = 0; kk < BK; ++kk) {
            float a[4], w[4];
            #pragma unroll
            for (int i = 0; i < 4; ++i) a[i] = As[kk][ty * 4 + i];
            #pragma unroll
            for (int j = 0; j < 4; ++j) w[j] = Ws[kk][tx * 4 + j];
            #pragma unroll
            for (int i = 0; i < 4; ++i)
                #pragma unroll
                for (int j = 0; j < 4; ++j)
                    acc[i][j] += a[i] * w[j];
        }
        __syncthreads();
    }

    #pragma unroll
    for (int i = 0; i < 4; ++i) {
        int r = row0 + ty * 4 + i;
        #pragma unroll
        for (int j = 0; j < 4; ++j) {
            int c = col0 + tx * 4 + j;
            C[(size_t)r * N + c] = acc[i][j] + bias[c];
        }
    }
}

// ---------------------------------------------------------------------------
// RMSNorm: one block per row. out[r, 0:ncols] = x * rsqrt(mean(x^2)+eps) * g
// in has row stride in_stride (to slice kv_a[:, :512]); out is dense.
// ---------------------------------------------------------------------------
__global__ void rmsnorm_k(const float* __restrict__ in, const float* __restrict__ g,
                          float* __restrict__ out, int ncols, int in_stride) {
    const int row = blockIdx.x;
    const float* x = in + (size_t)row * in_stride;
    float ss = 0.f;
    for (int c = threadIdx.x; c < ncols; c += blockDim.x) {
        float v = x[c];
        ss += v * v;
    }
    __shared__ float red[32];
    #pragma unroll
    for (int o = 16; o > 0; o >>= 1) ss += __shfl_xor_sync(0xffffffff, ss, o);
    if ((threadIdx.x & 31) == 0) red[threadIdx.x >> 5] = ss;
    __syncthreads();
    __shared__ float s_scale;
    if (threadIdx.x == 0) {
        float t = 0.f;
        int nw = blockDim.x >> 5;
        for (int i = 0; i < nw; ++i) t += red[i];
        s_scale = 1.0f / sqrtf(t / (float)ncols + 1e-20f);
    }
    __syncthreads();
    const float sc = s_scale;
    float* o = out + (size_t)row * ncols;
    for (int c = threadIdx.x; c < ncols; c += blockDim.x)
        o[c] = x[c] * sc * g[c];
}

// ---------------------------------------------------------------------------
// RoPE helper: angle for position s, rope-dim index d (0..63)
// inv_freq[i] = 10000^(-2i/64), cos/sin index = d % 32
// ---------------------------------------------------------------------------
__device__ __forceinline__ float rope_angle(int s, int fi) {
    return (float)s * powf(10000.0f, -(float)(2 * fi) / 64.0f);
}

// Q assemble: g_Q[b,h,s,d] ; d<64 = rope(q_b rope part), d>=64 = q_b nrope part
__global__ void assemble_q() {
    size_t idx = (size_t)blockIdx.x * blockDim.x + threadIdx.x;
    constexpr size_t total = (size_t)B_ * H_ * S_ * DH_;
    if (idx >= total) return;
    int d = (int)(idx % DH_);
    int s = (int)((idx / DH_) % S_);
    int h = (int)((idx / ((size_t)DH_ * S_)) % H_);
    int b = (int)(idx / ((size_t)DH_ * S_ * H_));
    const float* row = g_qb + ((size_t)(b * S_ + s)) * (H_ * DH_) + h * DH_;
    float val;
    if (d >= DR_) {
        val = row[d - DR_];                         // nrope: q_b dims 0..127
    } else {
        int fi = d & 31;
        float x   = row[DN_ + d];                   // rope part: q_b dims 128..191
        float rot = (d < 32) ? -row[DN_ + d + 32] : row[DN_ + d - 32];
        float ang = rope_angle(s, fi);
        val = x * cosf(ang) + rot * sinf(ang);
    }
    g_Q[idx] = val;
}

// K assemble: g_K[b,hkv,s,d] ; d<64 = rope(k_rope from kv_a), d>=64 = k_nrope
__global__ void assemble_k() {
    size_t idx = (size_t)blockIdx.x * blockDim.x + threadIdx.x;
    constexpr size_t total = (size_t)B_ * HKV_ * S_ * DH_;
    if (idx >= total) return;
    int d  = (int)(idx % DH_);
    int s  = (int)((idx / DH_) % S_);
    int hk = (int)((idx / ((size_t)DH_ * S_)) % HKV_);
    int b  = (int)(idx / ((size_t)DH_ * S_ * HKV_));
    float val;
    if (d >= DR_) {
        val = g_kvb[(size_t)(b * S_ + s) * (HKV_ * (DN_ + DV_)) + hk * (DN_ + DV_) + (d - DR_)];
    } else {
        int fi = d & 31;
        const float* kr = g_kva + (size_t)(b * S_ + s) * (RKV_ + DR_) + RKV_;
        float x   = kr[d];
        float rot = (d < 32) ? -kr[d + 32] : kr[d - 32];
        float ang = rope_angle(s, fi);
        val = x * cosf(ang) + rot * sinf(ang);
    }
    g_K[idx] = val;
}

// V assemble: g_V[b,hkv,s,d] = kv_b[..., 128+d]
__global__ void assemble_v() {
    size_t idx = (size_t)blockIdx.x * blockDim.x + threadIdx.x;
    constexpr size_t total = (size_t)B_ * HKV_ * S_ * DV_;
    if (idx >= total) return;
    int d  = (int)(idx % DV_);
    int s  = (int)((idx / DV_) % S_);
    int hk = (int)((idx / ((size_t)DV_ * S_)) % HKV_);
    int b  = (int)(idx / ((size_t)DV_ * S_ * HKV_));
    g_V[idx] = g_kvb[(size_t)(b * S_ + s) * (HKV_ * (DN_ + DV_)) + hk * (DN_ + DV_) + DN_ + d];
}

// ---------------------------------------------------------------------------
// Causal flash attention, fp32. One block = (b,h) x 64 query rows.
// Online softmax over 64-wide key tiles; O accumulator in registers.
// Writes g_attn[(b*S+s)*2048 + h*128 + d]  (ready for the o-proj GEMM).
// ---------------------------------------------------------------------------
__global__ void flash_attn() {
    constexpr int BR = 64, BC = 64;
    const int bh = blockIdx.x;       // 0..B*H-1
    const int qb = blockIdx.y;       // q-tile index
    const int b  = bh / H_;
    const int h  = bh % H_;
    const int hkv = h / G_;
    const float* Qp = g_Q + (((size_t)b * H_   + h  ) * S_) * DH_;
    const float* Kp = g_K + (((size_t)b * HKV_ + hkv) * S_) * DH_;
    const float* Vp = g_V + (((size_t)b * HKV_ + hkv) * S_) * DV_;
    const int q0 = qb * BR;

    __shared__ float Qs[16][BR + 1];
    __shared__ float Ks[16][BC + 1];
    __shared__ float Stile[BR][BC + 1];
    __shared__ float Vs[16][DV_ + 1];
    __shared__ float m_s[BR], l_s[BR], corr_s[BR];
    __shared__ float pmax[4][BR], psum[4][BR];

    const int tid = threadIdx.x;      // 256
    const int tx  = tid & 15;
    const int ty  = tid >> 4;

    float O[4][8];
    #pragma unroll
    for (int i = 0; i < 4; ++i)
        #pragma unroll
        for (int j = 0; j < 8; ++j) O[i][j] = 0.f;

    if (tid < BR) { m_s[tid] = -1e30f; l_s[tid] = 0.f; }
    __syncthreads();

    const float scale = 1.0f / sqrtf((float)DH_);
    const int ntiles = qb + 1;   // causal: key tiles 0..qb

    for (int t = 0; t < ntiles; ++t) {
        const int j0 = t * BC;

        // ---- scores: S = Q @ K^T over DH in chunks of 16 ----
        float Sacc[4][4] = {};
        for (int d0 = 0; d0 < DH_; d0 += 16) {
            #pragma unroll
            for (int it = 0; it < 4; ++it) {
                int i  = tid + it * 256;
                int kk = i & 15;
                int r  = i >> 4;
                Qs[kk][r] = Qp[(size_t)(q0 + r) * DH_ + d0 + kk];
                Ks[kk][r] = Kp[(size_t)(j0 + r) * DH_ + d0 + kk];
            }
            __syncthreads();
            #pragma unroll
            for (int kk = 0; kk < 16; ++kk) {
                float a[4], k4[4];
                #pragma unroll
                for (int i = 0; i < 4; ++i) a[i]  = Qs[kk][ty * 4 + i];
                #pragma unroll
                for (int j = 0; j < 4; ++j) k4[j] = Ks[kk][tx * 4 + j];
                #pragma unroll
                for (int i = 0; i < 4; ++i)
                    #pragma unroll
                    for (int j = 0; j < 4; ++j)
                        Sacc[i][j] += a[i] * k4[j];
            }
            __syncthreads();
        }

        // ---- scale + causal mask -> smem ----
        #pragma unroll
        for (int i = 0; i < 4; ++i) {
            int r = ty * 4 + i;
            #pragma unroll
            for (int j = 0; j < 4; ++j) {
                int c = tx * 4 + j;
                float v = Sacc[i][j] * scale;
                if (j0 + c > q0 + r) v = -1e9f;
                Stile[r][c] = v;
            }
        }
        __syncthreads();

        // ---- online softmax: row max (4 partial segments per row) ----
        {
            int row = tid & 63, seg = tid >> 6;
            float mx = -1e30f;
            #pragma unroll
            for (int c = 0; c < 16; ++c) mx = fmaxf(mx, Stile[row][seg * 16 + c]);
            pmax[seg][row] = mx;
        }
        __syncthreads();
        if (tid < BR) {
            float mo = m_s[tid];
            float mn = fmaxf(fmaxf(pmax[0][tid], pmax[1][tid]),
                             fmaxf(pmax[2][tid], pmax[3][tid]));
            mn = fmaxf(mo, mn);
            m_s[tid]   = mn;
            corr_s[tid] = expf(mo - mn);
        }
        __syncthreads();
        // exp in place + partial sums
        {
            int row = tid & 63, seg = tid >> 6;
            float mn = m_s[row];
            float sum = 0.f;
            #pragma unroll
            for (int c = 0; c < 16; ++c) {
                float e = expf(Stile[row][seg * 16 + c] - mn);
                Stile[row][seg * 16 + c] = e;
                sum += e;
            }
            psum[seg][row] = sum;
        }
        __syncthreads();
        if (tid < BR) {
            l_s[tid] = l_s[tid] * corr_s[tid] +
                       (psum[0][tid] + psum[1][tid] + psum[2][tid] + psum[3][tid]);
        }
        __syncthreads();

        // ---- rescale O, accumulate P @ V ----
        {
            float corr[4];
            #pragma unroll
            for (int i = 0; i < 4; ++i) corr[i] = corr_s[ty * 4 + i];
            #pragma unroll
            for (int i = 0; i < 4; ++i)
                #pragma unroll
                for (int j = 0; j < 8; ++j) O[i][j] *= corr[i];
        }
        for (int v0 = 0; v0 < BC; v0 += 16) {
            #pragma unroll
            for (int it = 0; it < 8; ++it) {
                int i  = tid + it * 256;
                int c  = i & 127;
                int kk = i >> 7;
                Vs[kk][c] = Vp[(size_t)(j0 + v0 + kk) * DV_ + c];
            }
            __syncthreads();
            #pragma unroll
            for (int kk = 0; kk < 16; ++kk) {
                float p[4], vv[8];
                #pragma unroll
                for (int i = 0; i < 4; ++i) p[i] = Stile[ty * 4 + i][v0 + kk];
                #pragma unroll
                for (int j = 0; j < 8; ++j) vv[j] = Vs[kk][tx * 8 + j];
                #pragma unroll
                for (int i = 0; i < 4; ++i)
                    #pragma unroll
                    for (int j = 0; j < 8; ++j)
                        O[i][j] += p[i] * vv[j];
            }
            __syncthreads();
        }
    }

    // ---- epilogue: divide by l, write [b, s, h, d] ----
    #pragma unroll
    for (int i = 0; i < 4; ++i) {
        int r = ty * 4 + i;
        float inv_l = 1.0f / l_s[r];
        size_t base = ((size_t)(b * S_) + q0 + r) * (H_ * DV_) + h * DV_;
        #pragma unroll
        for (int j = 0; j < 8; ++j)
            g_attn[base + tx * 8 + j] = O[i][j] * inv_l;
    }
}

// ---------------------------------------------------------------------------
// Launch sequence
// ---------------------------------------------------------------------------
extern "C" void kernel_launch(void* const* d_in, const int* in_sizes, int n_in,
                              void* d_out, int out_size) {
    const float* hs    = (const float*)d_in[0];
    // d_in[1] = attention_mask (tril causal; handled analytically)
    const float* w_qa  = (const float*)d_in[2];
    const float* b_qa  = (const float*)d_in[3];
    const float* gq    = (const float*)d_in[4];
    const float* w_qb  = (const float*)d_in[5];
    const float* b_qb  = (const float*)d_in[6];
    const float* w_kva = (const float*)d_in[7];
    const float* b_kva = (const float*)d_in[8];
    const float* gkv   = (const float*)d_in[9];
    const float* w_kvb = (const float*)d_in[10];
    const float* b_kvb = (const float*)d_in[11];
    const float* w_o   = (const float*)d_in[12];
    const float* b_o   = (const float*)d_in[13];
    float* out = (float*)d_out;

    float *p_qa, *p_qn, *p_qb, *p_kva, *p_kvn, *p_kvb, *p_attn;
    cudaGetSymbolAddress((void**)&p_qa,   g_qa);
    cudaGetSymbolAddress((void**)&p_qn,   g_qn);
    cudaGetSymbolAddress((void**)&p_qb,   g_qb);
    cudaGetSymbolAddress((void**)&p_kva,  g_kva);
    cudaGetSymbolAddress((void**)&p_kvn,  g_kvn);
    cudaGetSymbolAddress((void**)&p_kvb,  g_kvb);
    cudaGetSymbolAddress((void**)&p_attn, g_attn);

    // 1) q_a = hs @ w_qa + b_qa         [4096, 1024]
    sgemm_bias<<<dim3(RQ_ / 64, M_ / 64), 256>>>(hs, w_qa, b_qa, p_qa, M_, RQ_, D_);
    // 2) rmsnorm(q_a) * g_q             [4096, 1024]
    rmsnorm_k<<<M_, 256>>>(p_qa, gq, p_qn, RQ_, RQ_);
    // 3) q_b = qn @ w_qb + b_qb         [4096, 3072]
    sgemm_bias<<<dim3((H_ * DH_) / 64, M_ / 64), 256>>>(p_qn, w_qb, b_qb, p_qb, M_, H_ * DH_, RQ_);
    // 4) kv_a = hs @ w_kva + b_kva      [4096, 576]
    sgemm_bias<<<dim3((RKV_ + DR_) / 64, M_ / 64), 256>>>(hs, w_kva, b_kva, p_kva, M_, RKV_ + DR_, D_);
    // 5) rmsnorm(kv_a[:, :512]) * g_kv  [4096, 512]
    rmsnorm_k<<<M_, 256>>>(p_kva, gkv, p_kvn, RKV_, RKV_ + DR_);
    // 6) kv_b = kvn @ w_kvb + b_kvb     [4096, 1024]
    sgemm_bias<<<dim3((HKV_ * (DN_ + DV_)) / 64, M_ / 64), 256>>>(p_kvn, w_kvb, b_kvb, p_kvb, M_, HKV_ * (DN_ + DV_), RKV_);

    // 7) assemble Q / K / V with RoPE
    {
        constexpr size_t tq = (size_t)B_ * H_ * S_ * DH_;
        assemble_q<<<(unsigned)((tq + 255) / 256), 256>>>();
        constexpr size_t tk = (size_t)B_ * HKV_ * S_ * DH_;
        assemble_k<<<(unsigned)((tk + 255) / 256), 256>>>();
        constexpr size_t tv = (size_t)B_ * HKV_ * S_ * DV_;
        assemble_v<<<(unsigned)((tv + 255) / 256), 256>>>();
    }

    // 8) causal flash attention -> g_attn [4096, 2048]
    flash_attn<<<dim3(B_ * H_, S_ / 64), 256>>>();

    // 9) out = attn @ w_o + b_o          [4096, 2048]
    sgemm_bias<<<dim3(D_ / 64, M_ / 64), 256>>>(p_attn, w_o, b_o, out, M_, D_, D_);
}

// round 4
// speedup vs baseline: 1.3091x; 1.3091x over previous
#include <cuda_runtime.h>
#include <cuda_bf16.h>
#include <cstdint>
#include <math.h>

// ---------------------------------------------------------------------------
// Problem constants
// ---------------------------------------------------------------------------
namespace {
constexpr int B_   = 2;
constexpr int S_   = 2048;
constexpr int D_   = 2048;
constexpr int H_   = 16;
constexpr int HKV_ = 4;
constexpr int G_   = H_ / HKV_;
constexpr int RQ_  = 1024;
constexpr int RKV_ = 512;
constexpr int DH_  = 192;
constexpr int DR_  = 64;
constexpr int DN_  = 128;
constexpr int DV_  = 128;
constexpr int M_   = B_ * S_;          // 4096
constexpr int KVA_N    = RKV_ + DR_;   // 576 (true)
constexpr int KVA_NPAD = 640;          // padded to multiple of 128
}

// ---------------------------------------------------------------------------
// Scratch (static device globals)
// ---------------------------------------------------------------------------
__device__ float g_qa  [(size_t)M_ * RQ_];
__device__ float g_qn  [(size_t)M_ * RQ_];
__device__ float g_qb  [(size_t)M_ * H_ * DH_];
__device__ float g_kva [(size_t)M_ * KVA_NPAD];
__device__ float g_kvn [(size_t)M_ * RKV_];
__device__ float g_kvb [(size_t)M_ * HKV_ * (DN_ + DV_)];
__device__ float g_Q   [(size_t)B_ * H_   * S_ * DH_];
__device__ float g_K   [(size_t)B_ * HKV_ * S_ * DH_];
__device__ float g_V   [(size_t)B_ * HKV_ * S_ * DV_];
__device__ float g_attn[(size_t)M_ * H_ * DV_];
__device__ float g_bkva[KVA_NPAD];

// Pre-split / transposed weights: [N, K] bf16, hi + lo
__device__ __nv_bfloat16 g_wqa_h [(size_t)RQ_ * D_];
__device__ __nv_bfloat16 g_wqa_l [(size_t)RQ_ * D_];
__device__ __nv_bfloat16 g_wqb_h [(size_t)(H_ * DH_) * RQ_];
__device__ __nv_bfloat16 g_wqb_l [(size_t)(H_ * DH_) * RQ_];
__device__ __nv_bfloat16 g_wkva_h[(size_t)KVA_NPAD * D_];
__device__ __nv_bfloat16 g_wkva_l[(size_t)KVA_NPAD * D_];
__device__ __nv_bfloat16 g_wkvb_h[(size_t)(HKV_ * (DN_ + DV_)) * RKV_];
__device__ __nv_bfloat16 g_wkvb_l[(size_t)(HKV_ * (DN_ + DV_)) * RKV_];
__device__ __nv_bfloat16 g_wo_h  [(size_t)D_ * D_];
__device__ __nv_bfloat16 g_wo_l  [(size_t)D_ * D_];

// ---------------------------------------------------------------------------
// mma.sync helpers (sm_80+ PTX — legal on compute_100)
// ---------------------------------------------------------------------------
__device__ __forceinline__ uint32_t smem_u32(const void* p) {
    return (uint32_t)__cvta_generic_to_shared(p);
}
__device__ __forceinline__ void ldm_x4(uint32_t* r, uint32_t addr) {
    asm volatile("ldmatrix.sync.aligned.m8n8.x4.shared.b16 {%0,%1,%2,%3}, [%4];"
                 : "=r"(r[0]), "=r"(r[1]), "=r"(r[2]), "=r"(r[3]) : "r"(addr));
}
__device__ __forceinline__ void mma_bf16(float* c, const uint32_t* a, const uint32_t* b) {
    asm volatile("mma.sync.aligned.m16n8k16.row.col.f32.bf16.bf16.f32 "
                 "{%0,%1,%2,%3}, {%4,%5,%6,%7}, {%8,%9}, {%0,%1,%2,%3};"
                 : "+f"(c[0]), "+f"(c[1]), "+f"(c[2]), "+f"(c[3])
                 : "r"(a[0]), "r"(a[1]), "r"(a[2]), "r"(a[3]), "r"(b[0]), "r"(b[1]));
}
__device__ __forceinline__ uint32_t pack_bf2(__nv_bfloat16 a, __nv_bfloat16 b) {
    return (uint32_t)__bfloat16_as_ushort(a) | ((uint32_t)__bfloat16_as_ushort(b) << 16);
}

// ---------------------------------------------------------------------------
// Weight prep: transpose [K,N] fp32 -> [Npad,K] bf16 hi/lo split
// ---------------------------------------------------------------------------
__global__ void prep_w(const float* __restrict__ W, __nv_bfloat16* __restrict__ Hh,
                       __nv_bfloat16* __restrict__ Ll, int K, int N, int Npad) {
    __shared__ float t[32][33];
    const int kb = blockIdx.x * 32, nb = blockIdx.y * 32;
    const int tx = threadIdx.x, ty = threadIdx.y;   // 32 x 8
    #pragma unroll
    for (int i = 0; i < 4; ++i) {
        int k = kb + ty + i * 8;
        int n = nb + tx;
        t[ty + i * 8][tx] = (n < N) ? W[(size_t)k * N + n] : 0.f;
    }
    __syncthreads();
    #pragma unroll
    for (int i = 0; i < 4; ++i) {
        int n = nb + ty + i * 8;
        if (n >= Npad) continue;
        int k = kb + tx;
        float v = t[tx][ty + i * 8];
        __nv_bfloat16 h = __float2bfloat16(v);
        __nv_bfloat16 l = __float2bfloat16(v - __bfloat162float(h));
        Hh[(size_t)n * K + k] = h;
        Ll[(size_t)n * K + k] = l;
    }
}

__global__ void pad_bias_kva(const float* __restrict__ b) {
    int i = threadIdx.x + blockIdx.x * blockDim.x;
    if (i < KVA_NPAD) g_bkva[i] = (i < KVA_N) ? b[i] : 0.f;
}

// ---------------------------------------------------------------------------
// HMMA GEMM: C[M,N] = A[M,K](fp32, split on the fly) @ (Bh+Bl)[N,K]^T + bias
// Tiles 128x128x32. 8 warps in a 4(m) x 2(n) grid; each warp owns 32x64.
// Smem rows are 32 bf16 = 64B, padded to 80B stride -> ldmatrix conflict-free.
// ---------------------------------------------------------------------------
constexpr int ASTRIDE = 40;   // uint16 elements per smem row (80 bytes)

__global__ void __launch_bounds__(256)
gemm_mma(const float* __restrict__ A, const __nv_bfloat16* __restrict__ Bh,
         const __nv_bfloat16* __restrict__ Bl, const float* __restrict__ bias,
         float* __restrict__ C, int M, int N, int K) {
    __shared__ uint16_t As_h[128 * ASTRIDE];
    __shared__ uint16_t As_l[128 * ASTRIDE];
    __shared__ uint16_t Bs_h[128 * ASTRIDE];
    __shared__ uint16_t Bs_l[128 * ASTRIDE];

    const int tid  = threadIdx.x;
    const int lane = tid & 31;
    const int wid  = tid >> 5;
    const int wm   = wid & 3;        // warp row (32 m each)
    const int wn   = wid >> 2;       // warp col (64 n each)
    const int row0 = blockIdx.y * 128, col0 = blockIdx.x * 128;

    const uint32_t sAh = smem_u32(As_h), sAl = smem_u32(As_l);
    const uint32_t sBh = smem_u32(Bs_h), sBl = smem_u32(Bs_l);

    float acc[2][8][4];
    #pragma unroll
    for (int i = 0; i < 2; ++i)
        #pragma unroll
        for (int j = 0; j < 8; ++j)
            #pragma unroll
            for (int q = 0; q < 4; ++q) acc[i][j][q] = 0.f;

    // per-lane ldmatrix address offsets (element row/col within a 16x16 block)
    const int a_row = ((lane >> 3) & 1) * 8 + (lane & 7);   // 0..15
    const int a_kof = (lane >> 4) * 8;                      // 0 or 8
    const int b_row = (lane >> 4) * 8 + (lane & 7);         // n 0..15
    const int b_kof = ((lane >> 3) & 1) * 8;

    for (int k0 = 0; k0 < K; k0 += 32) {
        // ---- load + split A tile: 128 x 32 fp32 ----
        #pragma unroll
        for (int it = 0; it < 4; ++it) {
            int idx = tid + it * 256;        // 0..1023
            int r = idx >> 3, q = idx & 7;   // row, float4 index
            float4 v = *reinterpret_cast<const float4*>(
                A + (size_t)(row0 + r) * K + k0 + q * 4);
            __nv_bfloat16 h0 = __float2bfloat16(v.x);
            __nv_bfloat16 h1 = __float2bfloat16(v.y);
            __nv_bfloat16 h2 = __float2bfloat16(v.z);
            __nv_bfloat16 h3 = __float2bfloat16(v.w);
            __nv_bfloat16 l0 = __float2bfloat16(v.x - __bfloat162float(h0));
            __nv_bfloat16 l1 = __float2bfloat16(v.y - __bfloat162float(h1));
            __nv_bfloat16 l2 = __float2bfloat16(v.z - __bfloat162float(h2));
            __nv_bfloat16 l3 = __float2bfloat16(v.w - __bfloat162float(h3));
            int off = r * ASTRIDE + q * 4;
            *reinterpret_cast<uint2*>(As_h + off) = make_uint2(pack_bf2(h0, h1), pack_bf2(h2, h3));
            *reinterpret_cast<uint2*>(As_l + off) = make_uint2(pack_bf2(l0, l1), pack_bf2(l2, l3));
        }
        // ---- load B tiles: 128 x 32 bf16 (hi, lo) ----
        #pragma unroll
        for (int it = 0; it < 2; ++it) {
            int idx = tid + it * 256;        // 0..511
            int r = idx >> 2, q = idx & 3;   // row, uint4 index
            uint4 vh = *reinterpret_cast<const uint4*>(
                Bh + (size_t)(col0 + r) * K + k0 + q * 8);
            uint4 vl = *reinterpret_cast<const uint4*>(
                Bl + (size_t)(col0 + r) * K + k0 + q * 8);
            int off = r * ASTRIDE + q * 8;
            *reinterpret_cast<uint4*>(Bs_h + off) = vh;
            *reinterpret_cast<uint4*>(Bs_l + off) = vl;
        }
        __syncthreads();

        #pragma unroll
        for (int ks = 0; ks < 2; ++ks) {
            const int ke = ks * 16;
            uint32_t a_h[2][4], a_l[2][4];
            #pragma unroll
            for (int mi = 0; mi < 2; ++mi) {
                int r = wm * 32 + mi * 16 + a_row;
                uint32_t off = (uint32_t)(r * ASTRIDE + ke + a_kof) * 2;
                ldm_x4(a_h[mi], sAh + off);
                ldm_x4(a_l[mi], sAl + off);
            }
            #pragma unroll
            for (int nb = 0; nb < 4; ++nb) {
                int n = wn * 64 + nb * 16 + b_row;
                uint32_t off = (uint32_t)(n * ASTRIDE + ke + b_kof) * 2;
                uint32_t b_h[4], b_l[4];
                ldm_x4(b_h, sBh + off);
                ldm_x4(b_l, sBl + off);
                #pragma unroll
                for (int mi = 0; mi < 2; ++mi) {
                    mma_bf16(acc[mi][nb * 2 + 0], a_h[mi], b_h + 0);
                    mma_bf16(acc[mi][nb * 2 + 1], a_h[mi], b_h + 2);
                    mma_bf16(acc[mi][nb * 2 + 0], a_h[mi], b_l + 0);
                    mma_bf16(acc[mi][nb * 2 + 1], a_h[mi], b_l + 2);
                    mma_bf16(acc[mi][nb * 2 + 0], a_l[mi], b_h + 0);
                    mma_bf16(acc[mi][nb * 2 + 1], a_l[mi], b_h + 2);
                }
            }
        }
        __syncthreads();
    }

    // ---- epilogue: bias + store ----
    #pragma unroll
    for (int mi = 0; mi < 2; ++mi) {
        int r = row0 + wm * 32 + mi * 16 + (lane >> 2);
        #pragma unroll
        for (int nj = 0; nj < 8; ++nj) {
            int c = col0 + wn * 64 + nj * 8 + (lane & 3) * 2;
            float2 b2 = *reinterpret_cast<const float2*>(bias + c);
            float2 o0, o1;
            o0.x = acc[mi][nj][0] + b2.x;
            o0.y = acc[mi][nj][1] + b2.y;
            o1.x = acc[mi][nj][2] + b2.x;
            o1.y = acc[mi][nj][3] + b2.y;
            *reinterpret_cast<float2*>(C + (size_t)r * N + c)       = o0;
            *reinterpret_cast<float2*>(C + (size_t)(r + 8) * N + c) = o1;
        }
    }
}

// ---------------------------------------------------------------------------
// RMSNorm
// ---------------------------------------------------------------------------
__global__ void rmsnorm_k(const float* __restrict__ in, const float* __restrict__ g,
                          float* __restrict__ out, int ncols, int in_stride) {
    const int row = blockIdx.x;
    const float* x = in + (size_t)row * in_stride;
    float ss = 0.f;
    for (int c = threadIdx.x; c < ncols; c += blockDim.x) {
        float v = x[c];
        ss += v * v;
    }
    __shared__ float red[32];
    #pragma unroll
    for (int o = 16; o > 0; o >>= 1) ss += __shfl_xor_sync(0xffffffff, ss, o);
    if ((threadIdx.x & 31) == 0) red[threadIdx.x >> 5] = ss;
    __syncthreads();
    __shared__ float s_scale;
    if (threadIdx.x == 0) {
        float t = 0.f;
        int nw = blockDim.x >> 5;
        for (int i = 0; i < nw; ++i) t += red[i];
        s_scale = 1.0f / sqrtf(t / (float)ncols + 1e-20f);
    }
    __syncthreads();
    const float sc = s_scale;
    float* o = out + (size_t)row * ncols;
    for (int c = threadIdx.x; c < ncols; c += blockDim.x)
        o[c] = x[c] * sc * g[c];
}

// ---------------------------------------------------------------------------
// RoPE + assembles
// ---------------------------------------------------------------------------
__device__ __forceinline__ float rope_angle(int s, int fi) {
    return (float)s * powf(10000.0f, -(float)(2 * fi) / 64.0f);
}

__global__ void assemble_q() {
    size_t idx = (size_t)blockIdx.x * blockDim.x + threadIdx.x;
    constexpr size_t total = (size_t)B_ * H_ * S_ * DH_;
    if (idx >= total) return;
    int d = (int)(idx % DH_);
    int s = (int)((idx / DH_) % S_);
    int h = (int)((idx / ((size_t)DH_ * S_)) % H_);
    int b = (int)(idx / ((size_t)DH_ * S_ * H_));
    const float* row = g_qb + ((size_t)(b * S_ + s)) * (H_ * DH_) + h * DH_;
    float val;
    if (d >= DR_) {
        val = row[d - DR_];
    } else {
        int fi = d & 31;
        float x   = row[DN_ + d];
        float rot = (d < 32) ? -row[DN_ + d + 32] : row[DN_ + d - 32];
        float ang = rope_angle(s, fi);
        val = x * cosf(ang) + rot * sinf(ang);
    }
    g_Q[idx] = val;
}

__global__ void assemble_k() {
    size_t idx = (size_t)blockIdx.x * blockDim.x + threadIdx.x;
    constexpr size_t total = (size_t)B_ * HKV_ * S_ * DH_;
    if (idx >= total) return;
    int d  = (int)(idx % DH_);
    int s  = (int)((idx / DH_) % S_);
    int hk = (int)((idx / ((size_t)DH_ * S_)) % HKV_);
    int b  = (int)(idx / ((size_t)DH_ * S_ * HKV_));
    float val;
    if (d >= DR_) {
        val = g_kvb[(size_t)(b * S_ + s) * (HKV_ * (DN_ + DV_)) + hk * (DN_ + DV_) + (d - DR_)];
    } else {
        int fi = d & 31;
        const float* kr = g_kva + (size_t)(b * S_ + s) * KVA_NPAD + RKV_;
        float x   = kr[d];
        float rot = (d < 32) ? -kr[d + 32] : kr[d - 32];
        float ang = rope_angle(s, fi);
        val = x * cosf(ang) + rot * sinf(ang);
    }
    g_K[idx] = val;
}

__global__ void assemble_v() {
    size_t idx = (size_t)blockIdx.x * blockDim.x + threadIdx.x;
    constexpr size_t total = (size_t)B_ * HKV_ * S_ * DV_;
    if (idx >= total) return;
    int d  = (int)(idx % DV_);
    int s  = (int)((idx / DV_) % S_);
    int hk = (int)((idx / ((size_t)DV_ * S_)) % HKV_);
    int b  = (int)(idx / ((size_t)DV_ * S_ * HKV_));
    g_V[idx] = g_kvb[(size_t)(b * S_ + s) * (HKV_ * (DN_ + DV_)) + hk * (DN_ + DV_) + DN_ + d];
}

// ---------------------------------------------------------------------------
// Causal flash attention fp32
// ---------------------------------------------------------------------------
__global__ void flash_attn() {
    constexpr int BR = 64, BC = 64;
    const int bh = blockIdx.x;
    const int qb = blockIdx.y;
    const int b  = bh / H_;
    const int h  = bh % H_;
    const int hkv = h / G_;
    const float* Qp = g_Q + (((size_t)b * H_   + h  ) * S_) * DH_;
    const float* Kp = g_K + (((size_t)b * HKV_ + hkv) * S_) * DH_;
    const float* Vp = g_V + (((size_t)b * HKV_ + hkv) * S_) * DV_;
    const int q0 = qb * BR;

    __shared__ float Qs[16][BR + 1];
    __shared__ float Ks[16][BC + 1];
    __shared__ float Stile[BR][BC + 1];
    __shared__ float Vs[16][DV_ + 1];
    __shared__ float m_s[BR], l_s[BR], corr_s[BR];
    __shared__ float pmax[4][BR], psum[4][BR];

    const int tid = threadIdx.x;
    const int tx  = tid & 15;
    const int ty  = tid >> 4;

    float O[4][8];
    #pragma unroll
    for (int i = 0; i < 4; ++i)
        #pragma unroll
        for (int j = 0; j < 8; ++j) O[i][j] = 0.f;

    if (tid < BR) { m_s[tid] = -1e30f; l_s[tid] = 0.f; }
    __syncthreads();

    const float scale = 1.0f / sqrtf((float)DH_);
    const int ntiles = qb + 1;

    for (int t = 0; t < ntiles; ++t) {
        const int j0 = t * BC;

        float Sacc[4][4] = {};
        for (int d0 = 0; d0 < DH_; d0 += 16) {
            #pragma unroll
            for (int it = 0; it < 4; ++it) {
                int i  = tid + it * 256;
                int kk = i & 15;
                int r  = i >> 4;
                Qs[kk][r] = Qp[(size_t)(q0 + r) * DH_ + d0 + kk];
                Ks[kk][r] = Kp[(size_t)(j0 + r) * DH_ + d0 + kk];
            }
            __syncthreads();
            #pragma unroll
            for (int kk = 0; kk < 16; ++kk) {
                float a[4], k4[4];
                #pragma unroll
                for (int i = 0; i < 4; ++i) a[i]  = Qs[kk][ty * 4 + i];
                #pragma unroll
                for (int j = 0; j < 4; ++j) k4[j] = Ks[kk][tx * 4 + j];
                #pragma unroll
                for (int i = 0; i < 4; ++i)
                    #pragma unroll
                    for (int j = 0; j < 4; ++j)
                        Sacc[i][j] += a[i] * k4[j];
            }
            __syncthreads();
        }

        #pragma unroll
        for (int i = 0; i < 4; ++i) {
            int r = ty * 4 + i;
            #pragma unroll
            for (int j = 0; j < 4; ++j) {
                int c = tx * 4 + j;
                float v = Sacc[i][j] * scale;
                if (j0 + c > q0 + r) v = -1e9f;
                Stile[r][c] = v;
            }
        }
        __syncthreads();

        {
            int row = tid & 63, seg = tid >> 6;
            float mx = -1e30f;
            #pragma unroll
            for (int c = 0; c < 16; ++c) mx = fmaxf(mx, Stile[row][seg * 16 + c]);
            pmax[seg][row] = mx;
        }
        __syncthreads();
        if (tid < BR) {
            float mo = m_s[tid];
            float mn = fmaxf(fmaxf(pmax[0][tid], pmax[1][tid]),
                             fmaxf(pmax[2][tid], pmax[3][tid]));
            mn = fmaxf(mo, mn);
            m_s[tid]   = mn;
            corr_s[tid] = expf(mo - mn);
        }
        __syncthreads();
        {
            int row = tid & 63, seg = tid >> 6;
            float mn = m_s[row];
            float sum = 0.f;
            #pragma unroll
            for (int c = 0; c < 16; ++c) {
                float e = expf(Stile[row][seg * 16 + c] - mn);
                Stile[row][seg * 16 + c] = e;
                sum += e;
            }
            psum[seg][row] = sum;
        }
        __syncthreads();
        if (tid < BR) {
            l_s[tid] = l_s[tid] * corr_s[tid] +
                       (psum[0][tid] + psum[1][tid] + psum[2][tid] + psum[3][tid]);
        }
        __syncthreads();

        {
            float corr[4];
            #pragma unroll
            for (int i = 0; i < 4; ++i) corr[i] = corr_s[ty * 4 + i];
            #pragma unroll
            for (int i = 0; i < 4; ++i)
                #pragma unroll
                for (int j = 0; j < 8; ++j) O[i][j] *= corr[i];
        }
        for (int v0 = 0; v0 < BC; v0 += 16) {
            #pragma unroll
            for (int it = 0; it < 8; ++it) {
                int i  = tid + it * 256;
                int c  = i & 127;
                int kk = i >> 7;
                Vs[kk][c] = Vp[(size_t)(j0 + v0 + kk) * DV_ + c];
            }
            __syncthreads();
            #pragma unroll
            for (int kk = 0; kk < 16; ++kk) {
                float p[4], vv[8];
                #pragma unroll
                for (int i = 0; i < 4; ++i) p[i] = Stile[ty * 4 + i][v0 + kk];
                #pragma unroll
                for (int j = 0; j < 8; ++j) vv[j] = Vs[kk][tx * 8 + j];
                #pragma unroll
                for (int i = 0; i < 4; ++i)
                    #pragma unroll
                    for (int j = 0; j < 8; ++j)
                        O[i][j] += p[i] * vv[j];
            }
            __syncthreads();
        }
    }

    #pragma unroll
    for (int i = 0; i < 4; ++i) {
        int r = ty * 4 + i;
        float inv_l = 1.0f / l_s[r];
        size_t base = ((size_t)(b * S_) + q0 + r) * (H_ * DV_) + h * DV_;
        #pragma unroll
        for (int j = 0; j < 8; ++j)
            g_attn[base + tx * 8 + j] = O[i][j] * inv_l;
    }
}

// ---------------------------------------------------------------------------
// Launch sequence
// ---------------------------------------------------------------------------
extern "C" void kernel_launch(void* const* d_in, const int* in_sizes, int n_in,
                              void* d_out, int out_size) {
    const float* hs    = (const float*)d_in[0];
    const float* w_qa  = (const float*)d_in[2];
    const float* b_qa  = (const float*)d_in[3];
    const float* gq    = (const float*)d_in[4];
    const float* w_qb  = (const float*)d_in[5];
    const float* b_qb  = (const float*)d_in[6];
    const float* w_kva = (const float*)d_in[7];
    const float* b_kva = (const float*)d_in[8];
    const float* gkv   = (const float*)d_in[9];
    const float* w_kvb = (const float*)d_in[10];
    const float* b_kvb = (const float*)d_in[11];
    const float* w_o   = (const float*)d_in[12];
    const float* b_o   = (const float*)d_in[13];
    float* out = (float*)d_out;

    float *p_qa, *p_qn, *p_qb, *p_kva, *p_kvn, *p_kvb, *p_attn, *p_bkva;
    cudaGetSymbolAddress((void**)&p_qa,   g_qa);
    cudaGetSymbolAddress((void**)&p_qn,   g_qn);
    cudaGetSymbolAddress((void**)&p_qb,   g_qb);
    cudaGetSymbolAddress((void**)&p_kva,  g_kva);
    cudaGetSymbolAddress((void**)&p_kvn,  g_kvn);
    cudaGetSymbolAddress((void**)&p_kvb,  g_kvb);
    cudaGetSymbolAddress((void**)&p_attn, g_attn);
    cudaGetSymbolAddress((void**)&p_bkva, g_bkva);
    __nv_bfloat16 *qa_h, *qa_l, *qb_h, *qb_l, *kva_h, *kva_l, *kvb_h, *kvb_l, *o_h, *o_l;
    cudaGetSymbolAddress((void**)&qa_h,  g_wqa_h);  cudaGetSymbolAddress((void**)&qa_l,  g_wqa_l);
    cudaGetSymbolAddress((void**)&qb_h,  g_wqb_h);  cudaGetSymbolAddress((void**)&qb_l,  g_wqb_l);
    cudaGetSymbolAddress((void**)&kva_h, g_wkva_h); cudaGetSymbolAddress((void**)&kva_l, g_wkva_l);
    cudaGetSymbolAddress((void**)&kvb_h, g_wkvb_h); cudaGetSymbolAddress((void**)&kvb_l, g_wkvb_l);
    cudaGetSymbolAddress((void**)&o_h,   g_wo_h);   cudaGetSymbolAddress((void**)&o_l,   g_wo_l);

    // ---- weight prep (transpose + bf16 hi/lo split) ----
    dim3 tb(32, 8);
    prep_w<<<dim3(D_ / 32,  RQ_ / 32),           tb>>>(w_qa,  qa_h,  qa_l,  D_,  RQ_,       RQ_);
    prep_w<<<dim3(RQ_ / 32, (H_ * DH_) / 32),    tb>>>(w_qb,  qb_h,  qb_l,  RQ_, H_ * DH_,  H_ * DH_);
    prep_w<<<dim3(D_ / 32,  KVA_NPAD / 32),      tb>>>(w_kva, kva_h, kva_l, D_,  KVA_N,     KVA_NPAD);
    prep_w<<<dim3(RKV_ / 32, (HKV_ * 256) / 32), tb>>>(w_kvb, kvb_h, kvb_l, RKV_, HKV_ * 256, HKV_ * 256);
    prep_w<<<dim3(D_ / 32,  D_ / 32),            tb>>>(w_o,   o_h,   o_l,   D_,  D_,        D_);
    pad_bias_kva<<<(KVA_NPAD + 255) / 256, 256>>>(b_kva);

    // ---- projections on tensor cores (mma.sync bf16 hi/lo) ----
    gemm_mma<<<dim3(RQ_ / 128, M_ / 128), 256>>>(hs, qa_h, qa_l, b_qa, p_qa, M_, RQ_, D_);
    rmsnorm_k<<<M_, 256>>>(p_qa, gq, p_qn, RQ_, RQ_);
    gemm_mma<<<dim3((H_ * DH_) / 128, M_ / 128), 256>>>(p_qn, qb_h, qb_l, b_qb, p_qb, M_, H_ * DH_, RQ_);
    gemm_mma<<<dim3(KVA_NPAD / 128, M_ / 128), 256>>>(hs, kva_h, kva_l, p_bkva, p_kva, M_, KVA_NPAD, D_);
    rmsnorm_k<<<M_, 256>>>(p_kva, gkv, p_kvn, RKV_, KVA_NPAD);
    gemm_mma<<<dim3((HKV_ * 256) / 128, M_ / 128), 256>>>(p_kvn, kvb_h, kvb_l, b_kvb, p_kvb, M_, HKV_ * 256, RKV_);

    // ---- assemble Q/K/V with RoPE ----
    {
        constexpr size_t tq = (size_t)B_ * H_ * S_ * DH_;
        assemble_q<<<(unsigned)((tq + 255) / 256), 256>>>();
        constexpr size_t tk = (size_t)B_ * HKV_ * S_ * DH_;
        assemble_k<<<(unsigned)((tk + 255) / 256), 256>>>();
        constexpr size_t tv = (size_t)B_ * HKV_ * S_ * DV_;
        assemble_v<<<(unsigned)((tv + 255) / 256), 256>>>();
    }

    // ---- attention ----
    flash_attn<<<dim3(B_ * H_, S_ / 64), 256>>>();

    // ---- output projection ----
    gemm_mma<<<dim3(D_ / 128, M_ / 128), 256>>>(p_attn, o_h, o_l, b_o, out, M_, D_, D_);
}

// round 5
// speedup vs baseline: 2.5418x; 1.9416x over previous
#include <cuda_runtime.h>
#include <cuda_bf16.h>
#include <cstdint>
#include <math.h>

// ---------------------------------------------------------------------------
// Problem constants
// ---------------------------------------------------------------------------
namespace {
constexpr int B_   = 2;
constexpr int S_   = 2048;
constexpr int D_   = 2048;
constexpr int H_   = 16;
constexpr int HKV_ = 4;
constexpr int G_   = H_ / HKV_;
constexpr int RQ_  = 1024;
constexpr int RKV_ = 512;
constexpr int DH_  = 192;
constexpr int DR_  = 64;
constexpr int DN_  = 128;
constexpr int DV_  = 128;
constexpr int M_   = B_ * S_;          // 4096
constexpr int KVA_N    = RKV_ + DR_;   // 576
constexpr int KVA_NPAD = 640;
}

// ---------------------------------------------------------------------------
// Scratch (static device globals)
// ---------------------------------------------------------------------------
__device__ float g_qa  [(size_t)M_ * RQ_];
__device__ float g_qn  [(size_t)M_ * RQ_];
__device__ float g_qb  [(size_t)M_ * H_ * DH_];
__device__ float g_kva [(size_t)M_ * KVA_NPAD];
__device__ float g_kvn [(size_t)M_ * RKV_];
__device__ float g_kvb [(size_t)M_ * HKV_ * (DN_ + DV_)];
__device__ float g_attn[(size_t)M_ * H_ * DV_];
__device__ float g_bkva[KVA_NPAD];

// bf16 hi/lo Q/K ([b,h/hkv,s,d]) and V transposed ([b,hkv,d,s])
__device__ __nv_bfloat16 g_Qh [(size_t)B_ * H_   * S_ * DH_];
__device__ __nv_bfloat16 g_Ql [(size_t)B_ * H_   * S_ * DH_];
__device__ __nv_bfloat16 g_Kh [(size_t)B_ * HKV_ * S_ * DH_];
__device__ __nv_bfloat16 g_Kl [(size_t)B_ * HKV_ * S_ * DH_];
__device__ __nv_bfloat16 g_Vth[(size_t)B_ * HKV_ * DV_ * S_];
__device__ __nv_bfloat16 g_Vtl[(size_t)B_ * HKV_ * DV_ * S_];

// Pre-split / transposed weights: [N, K] bf16, hi + lo
__device__ __nv_bfloat16 g_wqa_h [(size_t)RQ_ * D_];
__device__ __nv_bfloat16 g_wqa_l [(size_t)RQ_ * D_];
__device__ __nv_bfloat16 g_wqb_h [(size_t)(H_ * DH_) * RQ_];
__device__ __nv_bfloat16 g_wqb_l [(size_t)(H_ * DH_) * RQ_];
__device__ __nv_bfloat16 g_wkva_h[(size_t)KVA_NPAD * D_];
__device__ __nv_bfloat16 g_wkva_l[(size_t)KVA_NPAD * D_];
__device__ __nv_bfloat16 g_wkvb_h[(size_t)(HKV_ * (DN_ + DV_)) * RKV_];
__device__ __nv_bfloat16 g_wkvb_l[(size_t)(HKV_ * (DN_ + DV_)) * RKV_];
__device__ __nv_bfloat16 g_wo_h  [(size_t)D_ * D_];
__device__ __nv_bfloat16 g_wo_l  [(size_t)D_ * D_];

// ---------------------------------------------------------------------------
// mma.sync helpers
// ---------------------------------------------------------------------------
__device__ __forceinline__ uint32_t smem_u32(const void* p) {
    return (uint32_t)__cvta_generic_to_shared(p);
}
__device__ __forceinline__ void ldm_x4(uint32_t* r, uint32_t addr) {
    asm volatile("ldmatrix.sync.aligned.m8n8.x4.shared.b16 {%0,%1,%2,%3}, [%4];"
                 : "=r"(r[0]), "=r"(r[1]), "=r"(r[2]), "=r"(r[3]) : "r"(addr));
}
__device__ __forceinline__ void mma_bf16(float* c, const uint32_t* a, const uint32_t* b) {
    asm volatile("mma.sync.aligned.m16n8k16.row.col.f32.bf16.bf16.f32 "
                 "{%0,%1,%2,%3}, {%4,%5,%6,%7}, {%8,%9}, {%0,%1,%2,%3};"
                 : "+f"(c[0]), "+f"(c[1]), "+f"(c[2]), "+f"(c[3])
                 : "r"(a[0]), "r"(a[1]), "r"(a[2]), "r"(a[3]), "r"(b[0]), "r"(b[1]));
}
__device__ __forceinline__ uint32_t pack_bf2(__nv_bfloat16 a, __nv_bfloat16 b) {
    return (uint32_t)__bfloat16_as_ushort(a) | ((uint32_t)__bfloat16_as_ushort(b) << 16);
}
__device__ __forceinline__ uint32_t pack_hi2(float x, float y) {
    return pack_bf2(__float2bfloat16(x), __float2bfloat16(y));
}
__device__ __forceinline__ uint32_t pack_lo2(float x, float y) {
    __nv_bfloat16 hx = __float2bfloat16(x), hy = __float2bfloat16(y);
    return pack_bf2(__float2bfloat16(x - __bfloat162float(hx)),
                    __float2bfloat16(y - __bfloat162float(hy)));
}

// ---------------------------------------------------------------------------
// Weight prep
// ---------------------------------------------------------------------------
__global__ void prep_w(const float* __restrict__ W, __nv_bfloat16* __restrict__ Hh,
                       __nv_bfloat16* __restrict__ Ll, int K, int N, int Npad) {
    __shared__ float t[32][33];
    const int kb = blockIdx.x * 32, nb = blockIdx.y * 32;
    const int tx = threadIdx.x, ty = threadIdx.y;
    #pragma unroll
    for (int i = 0; i < 4; ++i) {
        int k = kb + ty + i * 8;
        int n = nb + tx;
        t[ty + i * 8][tx] = (n < N) ? W[(size_t)k * N + n] : 0.f;
    }
    __syncthreads();
    #pragma unroll
    for (int i = 0; i < 4; ++i) {
        int n = nb + ty + i * 8;
        if (n >= Npad) continue;
        int k = kb + tx;
        float v = t[tx][ty + i * 8];
        __nv_bfloat16 h = __float2bfloat16(v);
        __nv_bfloat16 l = __float2bfloat16(v - __bfloat162float(h));
        Hh[(size_t)n * K + k] = h;
        Ll[(size_t)n * K + k] = l;
    }
}

__global__ void pad_bias_kva(const float* __restrict__ b) {
    int i = threadIdx.x + blockIdx.x * blockDim.x;
    if (i < KVA_NPAD) g_bkva[i] = (i < KVA_N) ? b[i] : 0.f;
}

// ---------------------------------------------------------------------------
// HMMA GEMM (unchanged from R4 — verified)
// ---------------------------------------------------------------------------
constexpr int ASTRIDE = 40;

__global__ void __launch_bounds__(256)
gemm_mma(const float* __restrict__ A, const __nv_bfloat16* __restrict__ Bh,
         const __nv_bfloat16* __restrict__ Bl, const float* __restrict__ bias,
         float* __restrict__ C, int M, int N, int K) {
    __shared__ uint16_t As_h[128 * ASTRIDE];
    __shared__ uint16_t As_l[128 * ASTRIDE];
    __shared__ uint16_t Bs_h[128 * ASTRIDE];
    __shared__ uint16_t Bs_l[128 * ASTRIDE];

    const int tid  = threadIdx.x;
    const int lane = tid & 31;
    const int wid  = tid >> 5;
    const int wm   = wid & 3;
    const int wn   = wid >> 2;
    const int row0 = blockIdx.y * 128, col0 = blockIdx.x * 128;

    const uint32_t sAh = smem_u32(As_h), sAl = smem_u32(As_l);
    const uint32_t sBh = smem_u32(Bs_h), sBl = smem_u32(Bs_l);

    float acc[2][8][4];
    #pragma unroll
    for (int i = 0; i < 2; ++i)
        #pragma unroll
        for (int j = 0; j < 8; ++j)
            #pragma unroll
            for (int q = 0; q < 4; ++q) acc[i][j][q] = 0.f;

    const int a_row = ((lane >> 3) & 1) * 8 + (lane & 7);
    const int a_kof = (lane >> 4) * 8;
    const int b_row = (lane >> 4) * 8 + (lane & 7);
    const int b_kof = ((lane >> 3) & 1) * 8;

    for (int k0 = 0; k0 < K; k0 += 32) {
        #pragma unroll
        for (int it = 0; it < 4; ++it) {
            int idx = tid + it * 256;
            int r = idx >> 3, q = idx & 7;
            float4 v = *reinterpret_cast<const float4*>(
                A + (size_t)(row0 + r) * K + k0 + q * 4);
            int off = r * ASTRIDE + q * 4;
            *reinterpret_cast<uint2*>(As_h + off) =
                make_uint2(pack_hi2(v.x, v.y), pack_hi2(v.z, v.w));
            *reinterpret_cast<uint2*>(As_l + off) =
                make_uint2(pack_lo2(v.x, v.y), pack_lo2(v.z, v.w));
        }
        #pragma unroll
        for (int it = 0; it < 2; ++it) {
            int idx = tid + it * 256;
            int r = idx >> 2, q = idx & 3;
            uint4 vh = *reinterpret_cast<const uint4*>(
                Bh + (size_t)(col0 + r) * K + k0 + q * 8);
            uint4 vl = *reinterpret_cast<const uint4*>(
                Bl + (size_t)(col0 + r) * K + k0 + q * 8);
            int off = r * ASTRIDE + q * 8;
            *reinterpret_cast<uint4*>(Bs_h + off) = vh;
            *reinterpret_cast<uint4*>(Bs_l + off) = vl;
        }
        __syncthreads();

        #pragma unroll
        for (int ks = 0; ks < 2; ++ks) {
            const int ke = ks * 16;
            uint32_t a_h[2][4], a_l[2][4];
            #pragma unroll
            for (int mi = 0; mi < 2; ++mi) {
                int r = wm * 32 + mi * 16 + a_row;
                uint32_t off = (uint32_t)(r * ASTRIDE + ke + a_kof) * 2;
                ldm_x4(a_h[mi], sAh + off);
                ldm_x4(a_l[mi], sAl + off);
            }
            #pragma unroll
            for (int nb = 0; nb < 4; ++nb) {
                int n = wn * 64 + nb * 16 + b_row;
                uint32_t off = (uint32_t)(n * ASTRIDE + ke + b_kof) * 2;
                uint32_t b_h[4], b_l[4];
                ldm_x4(b_h, sBh + off);
                ldm_x4(b_l, sBl + off);
                #pragma unroll
                for (int mi = 0; mi < 2; ++mi) {
                    mma_bf16(acc[mi][nb * 2 + 0], a_h[mi], b_h + 0);
                    mma_bf16(acc[mi][nb * 2 + 1], a_h[mi], b_h + 2);
                    mma_bf16(acc[mi][nb * 2 + 0], a_h[mi], b_l + 0);
                    mma_bf16(acc[mi][nb * 2 + 1], a_h[mi], b_l + 2);
                    mma_bf16(acc[mi][nb * 2 + 0], a_l[mi], b_h + 0);
                    mma_bf16(acc[mi][nb * 2 + 1], a_l[mi], b_h + 2);
                }
            }
        }
        __syncthreads();
    }

    #pragma unroll
    for (int mi = 0; mi < 2; ++mi) {
        int r = row0 + wm * 32 + mi * 16 + (lane >> 2);
        #pragma unroll
        for (int nj = 0; nj < 8; ++nj) {
            int c = col0 + wn * 64 + nj * 8 + (lane & 3) * 2;
            float2 b2 = *reinterpret_cast<const float2*>(bias + c);
            float2 o0, o1;
            o0.x = acc[mi][nj][0] + b2.x;
            o0.y = acc[mi][nj][1] + b2.y;
            o1.x = acc[mi][nj][2] + b2.x;
            o1.y = acc[mi][nj][3] + b2.y;
            *reinterpret_cast<float2*>(C + (size_t)r * N + c)       = o0;
            *reinterpret_cast<float2*>(C + (size_t)(r + 8) * N + c) = o1;
        }
    }
}

// ---------------------------------------------------------------------------
// RMSNorm
// ---------------------------------------------------------------------------
__global__ void rmsnorm_k(const float* __restrict__ in, const float* __restrict__ g,
                          float* __restrict__ out, int ncols, int in_stride) {
    const int row = blockIdx.x;
    const float* x = in + (size_t)row * in_stride;
    float ss = 0.f;
    for (int c = threadIdx.x; c < ncols; c += blockDim.x) {
        float v = x[c];
        ss += v * v;
    }
    __shared__ float red[32];
    #pragma unroll
    for (int o = 16; o > 0; o >>= 1) ss += __shfl_xor_sync(0xffffffff, ss, o);
    if ((threadIdx.x & 31) == 0) red[threadIdx.x >> 5] = ss;
    __syncthreads();
    __shared__ float s_scale;
    if (threadIdx.x == 0) {
        float t = 0.f;
        int nw = blockDim.x >> 5;
        for (int i = 0; i < nw; ++i) t += red[i];
        s_scale = 1.0f / sqrtf(t / (float)ncols + 1e-20f);
    }
    __syncthreads();
    const float sc = s_scale;
    float* o = out + (size_t)row * ncols;
    for (int c = threadIdx.x; c < ncols; c += blockDim.x)
        o[c] = x[c] * sc * g[c];
}

// ---------------------------------------------------------------------------
// RoPE + assembles -> bf16 hi/lo
// ---------------------------------------------------------------------------
__device__ __forceinline__ float rope_angle(int s, int fi) {
    return (float)s * powf(10000.0f, -(float)(2 * fi) / 64.0f);
}
__device__ __forceinline__ void split_store(__nv_bfloat16* Hh, __nv_bfloat16* Ll,
                                            size_t idx, float v) {
    __nv_bfloat16 h = __float2bfloat16(v);
    Hh[idx] = h;
    Ll[idx] = __float2bfloat16(v - __bfloat162float(h));
}

__global__ void assemble_q() {
    size_t idx = (size_t)blockIdx.x * blockDim.x + threadIdx.x;
    constexpr size_t total = (size_t)B_ * H_ * S_ * DH_;
    if (idx >= total) return;
    int d = (int)(idx % DH_);
    int s = (int)((idx / DH_) % S_);
    int h = (int)((idx / ((size_t)DH_ * S_)) % H_);
    int b = (int)(idx / ((size_t)DH_ * S_ * H_));
    const float* row = g_qb + ((size_t)(b * S_ + s)) * (H_ * DH_) + h * DH_;
    float val;
    if (d >= DR_) {
        val = row[d - DR_];
    } else {
        int fi = d & 31;
        float x   = row[DN_ + d];
        float rot = (d < 32) ? -row[DN_ + d + 32] : row[DN_ + d - 32];
        float ang = rope_angle(s, fi);
        val = x * cosf(ang) + rot * sinf(ang);
    }
    split_store(g_Qh, g_Ql, idx, val);
}

__global__ void assemble_k() {
    size_t idx = (size_t)blockIdx.x * blockDim.x + threadIdx.x;
    constexpr size_t total = (size_t)B_ * HKV_ * S_ * DH_;
    if (idx >= total) return;
    int d  = (int)(idx % DH_);
    int s  = (int)((idx / DH_) % S_);
    int hk = (int)((idx / ((size_t)DH_ * S_)) % HKV_);
    int b  = (int)(idx / ((size_t)DH_ * S_ * HKV_));
    float val;
    if (d >= DR_) {
        val = g_kvb[(size_t)(b * S_ + s) * (HKV_ * (DN_ + DV_)) + hk * (DN_ + DV_) + (d - DR_)];
    } else {
        int fi = d & 31;
        const float* kr = g_kva + (size_t)(b * S_ + s) * KVA_NPAD + RKV_;
        float x   = kr[d];
        float rot = (d < 32) ? -kr[d + 32] : kr[d - 32];
        float ang = rope_angle(s, fi);
        val = x * cosf(ang) + rot * sinf(ang);
    }
    split_store(g_Kh, g_Kl, idx, val);
}

// V transposed: [b, hkv, d, s]
__global__ void assemble_v() {
    size_t idx = (size_t)blockIdx.x * blockDim.x + threadIdx.x;
    constexpr size_t total = (size_t)B_ * HKV_ * DV_ * S_;
    if (idx >= total) return;
    int s  = (int)(idx % S_);
    int d  = (int)((idx / S_) % DV_);
    int hk = (int)((idx / ((size_t)S_ * DV_)) % HKV_);
    int b  = (int)(idx / ((size_t)S_ * DV_ * HKV_));
    float v = g_kvb[(size_t)(b * S_ + s) * (HKV_ * (DN_ + DV_)) + hk * (DN_ + DV_) + DN_ + d];
    split_store(g_Vth, g_Vtl, idx, v);
}

// ---------------------------------------------------------------------------
// Flash attention on mma.sync bf16 hi/lo.
// Block: 128 q-rows (8 warps x 16 rows), key tiles of 64. 186KB dyn smem.
// ---------------------------------------------------------------------------
constexpr int FA_QSTR = 200;   // smem stride (uint16) for Q/K (192 cols)
constexpr int FA_VSTR = 72;    // smem stride for Vt (64 cols)
constexpr int FA_SMEM = (2 * 128 * FA_QSTR + 2 * 64 * FA_QSTR + 2 * 128 * FA_VSTR) * 2;

__global__ void __launch_bounds__(256, 1)
flash_mma() {
    extern __shared__ __align__(16) uint16_t fs[];
    uint16_t* Qh = fs;
    uint16_t* Ql = Qh + 128 * FA_QSTR;
    uint16_t* Kh = Ql + 128 * FA_QSTR;
    uint16_t* Kl = Kh + 64 * FA_QSTR;
    uint16_t* Vh = Kl + 64 * FA_QSTR;
    uint16_t* Vl = Vh + 128 * FA_VSTR;

    const int bh = blockIdx.x;
    const int b  = bh / H_;
    const int h  = bh % H_;
    const int hkv = h / G_;
    const int qb = (int)gridDim.y - 1 - (int)blockIdx.y;   // heavy blocks first
    const int q0 = qb * 128;

    const int tid  = threadIdx.x;
    const int lane = tid & 31;
    const int wid  = tid >> 5;

    const __nv_bfloat16* Qhg = g_Qh + ((size_t)(b * H_ + h) * S_) * DH_;
    const __nv_bfloat16* Qlg = g_Ql + ((size_t)(b * H_ + h) * S_) * DH_;
    const __nv_bfloat16* Khg = g_Kh + ((size_t)(b * HKV_ + hkv) * S_) * DH_;
    const __nv_bfloat16* Klg = g_Kl + ((size_t)(b * HKV_ + hkv) * S_) * DH_;
    const __nv_bfloat16* Vhg = g_Vth + ((size_t)(b * HKV_ + hkv) * DV_) * S_;
    const __nv_bfloat16* Vlg = g_Vtl + ((size_t)(b * HKV_ + hkv) * DV_) * S_;

    // ---- load Q tile (128 x 192 hi/lo) ----
    {
        int r = tid >> 1, half = tid & 1;
        #pragma unroll
        for (int i = 0; i < 12; ++i) {
            int q = half * 12 + i;
            *reinterpret_cast<uint4*>(Qh + r * FA_QSTR + q * 8) =
                *reinterpret_cast<const uint4*>(Qhg + (size_t)(q0 + r) * DH_ + q * 8);
            *reinterpret_cast<uint4*>(Ql + r * FA_QSTR + q * 8) =
                *reinterpret_cast<const uint4*>(Qlg + (size_t)(q0 + r) * DH_ + q * 8);
        }
    }

    const int a_row = ((lane >> 3) & 1) * 8 + (lane & 7);
    const int a_kof = (lane >> 4) * 8;
    const int b_row = (lane >> 4) * 8 + (lane & 7);
    const int b_kof = ((lane >> 3) & 1) * 8;
    const int rl = lane >> 2, cb = (lane & 3) * 2;
    const int rg0 = q0 + wid * 16 + rl;          // global q row (lane's row 0)
    const float scale = rsqrtf((float)DH_);

    float accO[8][2][4];
    #pragma unroll
    for (int i = 0; i < 8; ++i)
        #pragma unroll
        for (int j = 0; j < 2; ++j)
            #pragma unroll
            for (int q = 0; q < 4; ++q) accO[i][j][q] = 0.f;
    float m0 = -1e30f, m1 = -1e30f, l0 = 0.f, l1 = 0.f;

    const int T = 2 * (qb + 1);
    for (int t = 0; t < T; ++t) {
        const int j0 = t * 64;
        __syncthreads();   // protect K/V smem from previous iteration's readers
        // ---- load K tile (64 x 192 hi/lo) ----
        {
            int r = tid >> 2, part = tid & 3;
            #pragma unroll
            for (int i = 0; i < 6; ++i) {
                int q = part * 6 + i;
                *reinterpret_cast<uint4*>(Kh + r * FA_QSTR + q * 8) =
                    *reinterpret_cast<const uint4*>(Khg + (size_t)(j0 + r) * DH_ + q * 8);
                *reinterpret_cast<uint4*>(Kl + r * FA_QSTR + q * 8) =
                    *reinterpret_cast<const uint4*>(Klg + (size_t)(j0 + r) * DH_ + q * 8);
            }
        }
        // ---- load Vt tile (128 x 64 hi/lo) ----
        {
            int r = tid >> 1, part = tid & 1;
            #pragma unroll
            for (int i = 0; i < 4; ++i) {
                int q = part * 4 + i;
                *reinterpret_cast<uint4*>(Vh + r * FA_VSTR + q * 8) =
                    *reinterpret_cast<const uint4*>(Vhg + (size_t)r * S_ + j0 + q * 8);
                *reinterpret_cast<uint4*>(Vl + r * FA_VSTR + q * 8) =
                    *reinterpret_cast<const uint4*>(Vlg + (size_t)r * S_ + j0 + q * 8);
            }
        }
        __syncthreads();

        // ---- S = Q K^T (hi/lo, fp32 accum) ----
        float Sc[4][2][4];
        #pragma unroll
        for (int i = 0; i < 4; ++i)
            #pragma unroll
            for (int j = 0; j < 2; ++j)
                #pragma unroll
                for (int q = 0; q < 4; ++q) Sc[i][j][q] = 0.f;

        #pragma unroll
        for (int ks = 0; ks < 12; ++ks) {
            uint32_t ah[4], al[4];
            uint32_t qoff = (uint32_t)((wid * 16 + a_row) * FA_QSTR + ks * 16 + a_kof) * 2;
            ldm_x4(ah, smem_u32(Qh) + qoff);
            ldm_x4(al, smem_u32(Ql) + qoff);
            #pragma unroll
            for (int nb = 0; nb < 4; ++nb) {
                uint32_t koff = (uint32_t)((nb * 16 + b_row) * FA_QSTR + ks * 16 + b_kof) * 2;
                uint32_t bh4[4], bl4[4];
                ldm_x4(bh4, smem_u32(Kh) + koff);
                ldm_x4(bl4, smem_u32(Kl) + koff);
                mma_bf16(Sc[nb][0], ah, bh4 + 0);
                mma_bf16(Sc[nb][1], ah, bh4 + 2);
                mma_bf16(Sc[nb][0], ah, bl4 + 0);
                mma_bf16(Sc[nb][1], ah, bl4 + 2);
                mma_bf16(Sc[nb][0], al, bh4 + 0);
                mma_bf16(Sc[nb][1], al, bh4 + 2);
            }
        }

        // ---- scale + causal mask ----
        const bool domask = (j0 + 63) > (q0 + wid * 16);
        #pragma unroll
        for (int nb = 0; nb < 4; ++nb)
            #pragma unroll
            for (int mm = 0; mm < 2; ++mm) {
                int c = j0 + nb * 16 + mm * 8 + cb;
                float* s4 = Sc[nb][mm];
                s4[0] *= scale; s4[1] *= scale; s4[2] *= scale; s4[3] *= scale;
                if (domask) {
                    if (c     > rg0)     s4[0] = -1e30f;
                    if (c + 1 > rg0)     s4[1] = -1e30f;
                    if (c     > rg0 + 8) s4[2] = -1e30f;
                    if (c + 1 > rg0 + 8) s4[3] = -1e30f;
                }
            }

        // ---- online softmax (rows warp-local) ----
        float mx0 = -1e30f, mx1 = -1e30f;
        #pragma unroll
        for (int nb = 0; nb < 4; ++nb)
            #pragma unroll
            for (int mm = 0; mm < 2; ++mm) {
                mx0 = fmaxf(mx0, fmaxf(Sc[nb][mm][0], Sc[nb][mm][1]));
                mx1 = fmaxf(mx1, fmaxf(Sc[nb][mm][2], Sc[nb][mm][3]));
            }
        mx0 = fmaxf(mx0, __shfl_xor_sync(0xffffffff, mx0, 1));
        mx0 = fmaxf(mx0, __shfl_xor_sync(0xffffffff, mx0, 2));
        mx1 = fmaxf(mx1, __shfl_xor_sync(0xffffffff, mx1, 1));
        mx1 = fmaxf(mx1, __shfl_xor_sync(0xffffffff, mx1, 2));
        float mn0 = fmaxf(m0, mx0), mn1 = fmaxf(m1, mx1);
        float corr0 = __expf(m0 - mn0), corr1 = __expf(m1 - mn1);
        m0 = mn0; m1 = mn1;

        uint32_t aPh[4][4], aPl[4][4];
        float sum0 = 0.f, sum1 = 0.f;
        #pragma unroll
        for (int nb = 0; nb < 4; ++nb) {
            float e00, e01, e02, e03, e10, e11, e12, e13;
            e00 = __expf(Sc[nb][0][0] - mn0);  e01 = __expf(Sc[nb][0][1] - mn0);
            e02 = __expf(Sc[nb][0][2] - mn1);  e03 = __expf(Sc[nb][0][3] - mn1);
            e10 = __expf(Sc[nb][1][0] - mn0);  e11 = __expf(Sc[nb][1][1] - mn0);
            e12 = __expf(Sc[nb][1][2] - mn1);  e13 = __expf(Sc[nb][1][3] - mn1);
            sum0 += e00 + e01 + e10 + e11;
            sum1 += e02 + e03 + e12 + e13;
            aPh[nb][0] = pack_hi2(e00, e01);  aPl[nb][0] = pack_lo2(e00, e01);
            aPh[nb][1] = pack_hi2(e02, e03);  aPl[nb][1] = pack_lo2(e02, e03);
            aPh[nb][2] = pack_hi2(e10, e11);  aPl[nb][2] = pack_lo2(e10, e11);
            aPh[nb][3] = pack_hi2(e12, e13);  aPl[nb][3] = pack_lo2(e12, e13);
        }
        sum0 += __shfl_xor_sync(0xffffffff, sum0, 1);
        sum0 += __shfl_xor_sync(0xffffffff, sum0, 2);
        sum1 += __shfl_xor_sync(0xffffffff, sum1, 1);
        sum1 += __shfl_xor_sync(0xffffffff, sum1, 2);
        l0 = l0 * corr0 + sum0;
        l1 = l1 * corr1 + sum1;

        // ---- rescale O ----
        #pragma unroll
        for (int nv = 0; nv < 8; ++nv)
            #pragma unroll
            for (int mm = 0; mm < 2; ++mm) {
                accO[nv][mm][0] *= corr0; accO[nv][mm][1] *= corr0;
                accO[nv][mm][2] *= corr1; accO[nv][mm][3] *= corr1;
            }

        // ---- O += P V (hi/lo) ----
        #pragma unroll
        for (int ks = 0; ks < 4; ++ks) {
            #pragma unroll
            for (int nv = 0; nv < 8; ++nv) {
                uint32_t voff = (uint32_t)((nv * 16 + b_row) * FA_VSTR + ks * 16 + b_kof) * 2;
                uint32_t bh4[4], bl4[4];
                ldm_x4(bh4, smem_u32(Vh) + voff);
                ldm_x4(bl4, smem_u32(Vl) + voff);
                mma_bf16(accO[nv][0], aPh[ks], bh4 + 0);
                mma_bf16(accO[nv][1], aPh[ks], bh4 + 2);
                mma_bf16(accO[nv][0], aPh[ks], bl4 + 0);
                mma_bf16(accO[nv][1], aPh[ks], bl4 + 2);
                mma_bf16(accO[nv][0], aPl[ks], bh4 + 0);
                mma_bf16(accO[nv][1], aPl[ks], bh4 + 2);
            }
        }
    }

    // ---- epilogue ----
    const float il0 = 1.0f / l0, il1 = 1.0f / l1;
    #pragma unroll
    for (int nv = 0; nv < 8; ++nv)
        #pragma unroll
        for (int mm = 0; mm < 2; ++mm) {
            int c = nv * 16 + mm * 8 + cb;
            size_t base0 = ((size_t)(b * S_) + rg0)     * (H_ * DV_) + h * DV_ + c;
            size_t base1 = ((size_t)(b * S_) + rg0 + 8) * (H_ * DV_) + h * DV_ + c;
            float2 o0 = make_float2(accO[nv][mm][0] * il0, accO[nv][mm][1] * il0);
            float2 o1 = make_float2(accO[nv][mm][2] * il1, accO[nv][mm][3] * il1);
            *reinterpret_cast<float2*>(g_attn + base0) = o0;
            *reinterpret_cast<float2*>(g_attn + base1) = o1;
        }
}

// ---------------------------------------------------------------------------
// Launch sequence
// ---------------------------------------------------------------------------
extern "C" void kernel_launch(void* const* d_in, const int* in_sizes, int n_in,
                              void* d_out, int out_size) {
    const float* hs    = (const float*)d_in[0];
    const float* w_qa  = (const float*)d_in[2];
    const float* b_qa  = (const float*)d_in[3];
    const float* gq    = (const float*)d_in[4];
    const float* w_qb  = (const float*)d_in[5];
    const float* b_qb  = (const float*)d_in[6];
    const float* w_kva = (const float*)d_in[7];
    const float* b_kva = (const float*)d_in[8];
    const float* gkv   = (const float*)d_in[9];
    const float* w_kvb = (const float*)d_in[10];
    const float* b_kvb = (const float*)d_in[11];
    const float* w_o   = (const float*)d_in[12];
    const float* b_o   = (const float*)d_in[13];
    float* out = (float*)d_out;

    float *p_qa, *p_qn, *p_qb, *p_kva, *p_kvn, *p_kvb, *p_attn, *p_bkva;
    cudaGetSymbolAddress((void**)&p_qa,   g_qa);
    cudaGetSymbolAddress((void**)&p_qn,   g_qn);
    cudaGetSymbolAddress((void**)&p_qb,   g_qb);
    cudaGetSymbolAddress((void**)&p_kva,  g_kva);
    cudaGetSymbolAddress((void**)&p_kvn,  g_kvn);
    cudaGetSymbolAddress((void**)&p_kvb,  g_kvb);
    cudaGetSymbolAddress((void**)&p_attn, g_attn);
    cudaGetSymbolAddress((void**)&p_bkva, g_bkva);
    __nv_bfloat16 *qa_h, *qa_l, *qb_h, *qb_l, *kva_h, *kva_l, *kvb_h, *kvb_l, *o_h, *o_l;
    cudaGetSymbolAddress((void**)&qa_h,  g_wqa_h);  cudaGetSymbolAddress((void**)&qa_l,  g_wqa_l);
    cudaGetSymbolAddress((void**)&qb_h,  g_wqb_h);  cudaGetSymbolAddress((void**)&qb_l,  g_wqb_l);
    cudaGetSymbolAddress((void**)&kva_h, g_wkva_h); cudaGetSymbolAddress((void**)&kva_l, g_wkva_l);
    cudaGetSymbolAddress((void**)&kvb_h, g_wkvb_h); cudaGetSymbolAddress((void**)&kvb_l, g_wkvb_l);
    cudaGetSymbolAddress((void**)&o_h,   g_wo_h);   cudaGetSymbolAddress((void**)&o_l,   g_wo_l);

    cudaFuncSetAttribute(flash_mma, cudaFuncAttributeMaxDynamicSharedMemorySize, FA_SMEM);

    // ---- weight prep ----
    dim3 tb(32, 8);
    prep_w<<<dim3(D_ / 32,  RQ_ / 32),           tb>>>(w_qa,  qa_h,  qa_l,  D_,  RQ_,       RQ_);
    prep_w<<<dim3(RQ_ / 32, (H_ * DH_) / 32),    tb>>>(w_qb,  qb_h,  qb_l,  RQ_, H_ * DH_,  H_ * DH_);
    prep_w<<<dim3(D_ / 32,  KVA_NPAD / 32),      tb>>>(w_kva, kva_h, kva_l, D_,  KVA_N,     KVA_NPAD);
    prep_w<<<dim3(RKV_ / 32, (HKV_ * 256) / 32), tb>>>(w_kvb, kvb_h, kvb_l, RKV_, HKV_ * 256, HKV_ * 256);
    prep_w<<<dim3(D_ / 32,  D_ / 32),            tb>>>(w_o,   o_h,   o_l,   D_,  D_,        D_);
    pad_bias_kva<<<(KVA_NPAD + 255) / 256, 256>>>(b_kva);

    // ---- projections ----
    gemm_mma<<<dim3(RQ_ / 128, M_ / 128), 256>>>(hs, qa_h, qa_l, b_qa, p_qa, M_, RQ_, D_);
    rmsnorm_k<<<M_, 256>>>(p_qa, gq, p_qn, RQ_, RQ_);
    gemm_mma<<<dim3((H_ * DH_) / 128, M_ / 128), 256>>>(p_qn, qb_h, qb_l, b_qb, p_qb, M_, H_ * DH_, RQ_);
    gemm_mma<<<dim3(KVA_NPAD / 128, M_ / 128), 256>>>(hs, kva_h, kva_l, p_bkva, p_kva, M_, KVA_NPAD, D_);
    rmsnorm_k<<<M_, 256>>>(p_kva, gkv, p_kvn, RKV_, KVA_NPAD);
    gemm_mma<<<dim3((HKV_ * 256) / 128, M_ / 128), 256>>>(p_kvn, kvb_h, kvb_l, b_kvb, p_kvb, M_, HKV_ * 256, RKV_);

    // ---- assemble Q/K/V (bf16 hi/lo; V transposed) ----
    {
        constexpr size_t tq = (size_t)B_ * H_ * S_ * DH_;
        assemble_q<<<(unsigned)((tq + 255) / 256), 256>>>();
        constexpr size_t tk = (size_t)B_ * HKV_ * S_ * DH_;
        assemble_k<<<(unsigned)((tk + 255) / 256), 256>>>();
        constexpr size_t tv = (size_t)B_ * HKV_ * DV_ * S_;
        assemble_v<<<(unsigned)((tv + 255) / 256), 256>>>();
    }

    // ---- attention (tensor-core flash) ----
    flash_mma<<<dim3(B_ * H_, S_ / 128), 256, FA_SMEM>>>();

    // ---- output projection ----
    gemm_mma<<<dim3(D_ / 128, M_ / 128), 256>>>(p_attn, o_h, o_l, b_o, out, M_, D_, D_);
}

// round 6
// speedup vs baseline: 2.9845x; 1.1742x over previous
#include <cuda_runtime.h>
#include <cuda_bf16.h>
#include <cstdint>
#include <math.h>

// ---------------------------------------------------------------------------
// Problem constants
// ---------------------------------------------------------------------------
namespace {
constexpr int B_   = 2;
constexpr int S_   = 2048;
constexpr int D_   = 2048;
constexpr int H_   = 16;
constexpr int HKV_ = 4;
constexpr int G_   = H_ / HKV_;
constexpr int RQ_  = 1024;
constexpr int RKV_ = 512;
constexpr int DH_  = 192;
constexpr int DR_  = 64;
constexpr int DN_  = 128;
constexpr int DV_  = 128;
constexpr int M_   = B_ * S_;          // 4096
constexpr int KVA_N    = RKV_ + DR_;   // 576
constexpr int KVA_NPAD = 640;
}

// ---------------------------------------------------------------------------
// Scratch (static device globals)
// ---------------------------------------------------------------------------
__device__ float g_qa  [(size_t)M_ * RQ_];
__device__ float g_qb  [(size_t)M_ * H_ * DH_];
__device__ float g_kva [(size_t)M_ * KVA_NPAD];
__device__ float g_kvb [(size_t)M_ * HKV_ * (DN_ + DV_)];
__device__ float g_bkva[KVA_NPAD];

// pre-split activations (bf16 hi/lo)
__device__ __nv_bfloat16 g_hsh [(size_t)M_ * D_];
__device__ __nv_bfloat16 g_hsl [(size_t)M_ * D_];
__device__ __nv_bfloat16 g_qnh [(size_t)M_ * RQ_];
__device__ __nv_bfloat16 g_qnl [(size_t)M_ * RQ_];
__device__ __nv_bfloat16 g_kvnh[(size_t)M_ * RKV_];
__device__ __nv_bfloat16 g_kvnl[(size_t)M_ * RKV_];
__device__ __nv_bfloat16 g_atth[(size_t)M_ * H_ * DV_];
__device__ __nv_bfloat16 g_attl[(size_t)M_ * H_ * DV_];

// bf16 hi/lo Q/K ([b,h/hkv,s,d]) and V transposed ([b,hkv,d,s])
__device__ __nv_bfloat16 g_Qh [(size_t)B_ * H_   * S_ * DH_];
__device__ __nv_bfloat16 g_Ql [(size_t)B_ * H_   * S_ * DH_];
__device__ __nv_bfloat16 g_Kh [(size_t)B_ * HKV_ * S_ * DH_];
__device__ __nv_bfloat16 g_Kl [(size_t)B_ * HKV_ * S_ * DH_];
__device__ __nv_bfloat16 g_Vth[(size_t)B_ * HKV_ * DV_ * S_];
__device__ __nv_bfloat16 g_Vtl[(size_t)B_ * HKV_ * DV_ * S_];

// Pre-split / transposed weights: [N, K] bf16, hi + lo
__device__ __nv_bfloat16 g_wqa_h [(size_t)RQ_ * D_];
__device__ __nv_bfloat16 g_wqa_l [(size_t)RQ_ * D_];
__device__ __nv_bfloat16 g_wqb_h [(size_t)(H_ * DH_) * RQ_];
__device__ __nv_bfloat16 g_wqb_l [(size_t)(H_ * DH_) * RQ_];
__device__ __nv_bfloat16 g_wkva_h[(size_t)KVA_NPAD * D_];
__device__ __nv_bfloat16 g_wkva_l[(size_t)KVA_NPAD * D_];
__device__ __nv_bfloat16 g_wkvb_h[(size_t)(HKV_ * (DN_ + DV_)) * RKV_];
__device__ __nv_bfloat16 g_wkvb_l[(size_t)(HKV_ * (DN_ + DV_)) * RKV_];
__device__ __nv_bfloat16 g_wo_h  [(size_t)D_ * D_];
__device__ __nv_bfloat16 g_wo_l  [(size_t)D_ * D_];

// ---------------------------------------------------------------------------
// mma.sync / cp.async helpers
// ---------------------------------------------------------------------------
__device__ __forceinline__ uint32_t smem_u32(const void* p) {
    return (uint32_t)__cvta_generic_to_shared(p);
}
__device__ __forceinline__ void ldm_x4(uint32_t* r, uint32_t addr) {
    asm volatile("ldmatrix.sync.aligned.m8n8.x4.shared.b16 {%0,%1,%2,%3}, [%4];"
                 : "=r"(r[0]), "=r"(r[1]), "=r"(r[2]), "=r"(r[3]) : "r"(addr));
}
__device__ __forceinline__ void mma_bf16(float* c, const uint32_t* a, const uint32_t* b) {
    asm volatile("mma.sync.aligned.m16n8k16.row.col.f32.bf16.bf16.f32 "
                 "{%0,%1,%2,%3}, {%4,%5,%6,%7}, {%8,%9}, {%0,%1,%2,%3};"
                 : "+f"(c[0]), "+f"(c[1]), "+f"(c[2]), "+f"(c[3])
                 : "r"(a[0]), "r"(a[1]), "r"(a[2]), "r"(a[3]), "r"(b[0]), "r"(b[1]));
}
__device__ __forceinline__ void cp16(uint32_t dst, const void* src) {
    asm volatile("cp.async.cg.shared.global [%0], [%1], 16;"
                 :: "r"(dst), "l"(__cvta_generic_to_global(src)));
}
__device__ __forceinline__ void cp_commit() {
    asm volatile("cp.async.commit_group;");
}
template <int N_> __device__ __forceinline__ void cp_wait() {
    asm volatile("cp.async.wait_group %0;" :: "n"(N_));
}
__device__ __forceinline__ uint32_t pack_bf2(__nv_bfloat16 a, __nv_bfloat16 b) {
    return (uint32_t)__bfloat16_as_ushort(a) | ((uint32_t)__bfloat16_as_ushort(b) << 16);
}
__device__ __forceinline__ uint32_t pack_hi2(float x, float y) {
    return pack_bf2(__float2bfloat16(x), __float2bfloat16(y));
}
__device__ __forceinline__ uint32_t pack_lo2(float x, float y) {
    __nv_bfloat16 hx = __float2bfloat16(x), hy = __float2bfloat16(y);
    return pack_bf2(__float2bfloat16(x - __bfloat162float(hx)),
                    __float2bfloat16(y - __bfloat162float(hy)));
}
__device__ __forceinline__ void split_store(__nv_bfloat16* Hh, __nv_bfloat16* Ll,
                                            size_t idx, float v) {
    __nv_bfloat16 h = __float2bfloat16(v);
    Hh[idx] = h;
    Ll[idx] = __float2bfloat16(v - __bfloat162float(h));
}

// ---------------------------------------------------------------------------
// Weight prep + activation split
// ---------------------------------------------------------------------------
__global__ void prep_w(const float* __restrict__ W, __nv_bfloat16* __restrict__ Hh,
                       __nv_bfloat16* __restrict__ Ll, int K, int N, int Npad) {
    __shared__ float t[32][33];
    const int kb = blockIdx.x * 32, nb = blockIdx.y * 32;
    const int tx = threadIdx.x, ty = threadIdx.y;
    #pragma unroll
    for (int i = 0; i < 4; ++i) {
        int k = kb + ty + i * 8;
        int n = nb + tx;
        t[ty + i * 8][tx] = (n < N) ? W[(size_t)k * N + n] : 0.f;
    }
    __syncthreads();
    #pragma unroll
    for (int i = 0; i < 4; ++i) {
        int n = nb + ty + i * 8;
        if (n >= Npad) continue;
        int k = kb + tx;
        float v = t[tx][ty + i * 8];
        split_store(Hh, Ll, (size_t)n * K + k, v);
    }
}

__global__ void pad_bias_kva(const float* __restrict__ b) {
    int i = threadIdx.x + blockIdx.x * blockDim.x;
    if (i < KVA_NPAD) g_bkva[i] = (i < KVA_N) ? b[i] : 0.f;
}

__global__ void split_act(const float* __restrict__ X, __nv_bfloat16* __restrict__ Hh,
                          __nv_bfloat16* __restrict__ Ll, size_t total) {
    size_t i = (size_t)blockIdx.x * blockDim.x + threadIdx.x;
    if (i < total) split_store(Hh, Ll, i, X[i]);
}

// ---------------------------------------------------------------------------
// HMMA GEMM, cp.async double-buffered.
// C[M,N] = (Ah+Al)[M,K] @ (Bh+Bl)[N,K]^T + bias   (3-product hi/lo, fp32 acc)
// Tiles 128x128x32; 8 warps 4(m)x2(n), each 32x64.
// ---------------------------------------------------------------------------
constexpr int ASTRIDE = 40;                       // uint16 per smem row (80B)
constexpr int GARR    = 128 * ASTRIDE;            // uint16 per array
constexpr int GEMM_SMEM2 = 2 * 4 * GARR * 2;      // 2 stages x 4 arrays, bytes

__global__ void __launch_bounds__(256)
gemm_mma2(const __nv_bfloat16* __restrict__ Agh, const __nv_bfloat16* __restrict__ Agl,
          const __nv_bfloat16* __restrict__ Bgh, const __nv_bfloat16* __restrict__ Bgl,
          const float* __restrict__ bias, float* __restrict__ C,
          int M, int N, int K) {
    extern __shared__ __align__(16) uint16_t gs[];
    const int tid  = threadIdx.x;
    const int lane = tid & 31;
    const int wid  = tid >> 5;
    const int wm   = wid & 3;
    const int wn   = wid >> 2;
    const int row0 = blockIdx.y * 128, col0 = blockIdx.x * 128;
    const uint32_t sb = smem_u32(gs);

    float acc[2][8][4];
    #pragma unroll
    for (int i = 0; i < 2; ++i)
        #pragma unroll
        for (int j = 0; j < 8; ++j)
            #pragma unroll
            for (int q = 0; q < 4; ++q) acc[i][j][q] = 0.f;

    const int a_row = ((lane >> 3) & 1) * 8 + (lane & 7);
    const int a_kof = (lane >> 4) * 8;
    const int b_row = (lane >> 4) * 8 + (lane & 7);
    const int b_kof = ((lane >> 3) & 1) * 8;

    const int nch = K >> 5;

    auto prefetch = [&](int c) {
        const int k0 = c << 5;
        const int s = c & 1;
        #pragma unroll
        for (int it = 0; it < 8; ++it) {
            int idx = tid + it * 256;
            int arr = idx >> 9;                 // 0 Ah, 1 Al, 2 Bh, 3 Bl
            int j   = idx & 511;
            int r   = j >> 2, q = j & 3;
            const __nv_bfloat16* src = (arr == 0) ? Agh : (arr == 1) ? Agl
                                     : (arr == 2) ? Bgh : Bgl;
            size_t goff = (size_t)(((arr < 2) ? row0 : col0) + r) * K + k0 + q * 8;
            uint32_t dst = sb + (uint32_t)(((s * 4 + arr) * 128 + r) * ASTRIDE + q * 8) * 2;
            cp16(dst, src + goff);
        }
        cp_commit();
    };

    prefetch(0);
    for (int c = 0; c < nch; ++c) {
        if (c + 1 < nch) { prefetch(c + 1); cp_wait<1>(); }
        else             { cp_wait<0>(); }
        __syncthreads();

        const uint32_t base = sb + (uint32_t)((c & 1) * 4 * GARR) * 2;
        const uint32_t sAh = base;
        const uint32_t sAl = base + (uint32_t)GARR * 2;
        const uint32_t sBh = base + (uint32_t)GARR * 4;
        const uint32_t sBl = base + (uint32_t)GARR * 6;

        #pragma unroll
        for (int ks = 0; ks < 2; ++ks) {
            const int ke = ks * 16;
            uint32_t a_h[2][4], a_l[2][4];
            #pragma unroll
            for (int mi = 0; mi < 2; ++mi) {
                int r = wm * 32 + mi * 16 + a_row;
                uint32_t off = (uint32_t)(r * ASTRIDE + ke + a_kof) * 2;
                ldm_x4(a_h[mi], sAh + off);
                ldm_x4(a_l[mi], sAl + off);
            }
            #pragma unroll
            for (int nb = 0; nb < 4; ++nb) {
                int n = wn * 64 + nb * 16 + b_row;
                uint32_t off = (uint32_t)(n * ASTRIDE + ke + b_kof) * 2;
                uint32_t b_h[4], b_l[4];
                ldm_x4(b_h, sBh + off);
                ldm_x4(b_l, sBl + off);
                #pragma unroll
                for (int mi = 0; mi < 2; ++mi) {
                    mma_bf16(acc[mi][nb * 2 + 0], a_h[mi], b_h + 0);
                    mma_bf16(acc[mi][nb * 2 + 1], a_h[mi], b_h + 2);
                    mma_bf16(acc[mi][nb * 2 + 0], a_h[mi], b_l + 0);
                    mma_bf16(acc[mi][nb * 2 + 1], a_h[mi], b_l + 2);
                    mma_bf16(acc[mi][nb * 2 + 0], a_l[mi], b_h + 0);
                    mma_bf16(acc[mi][nb * 2 + 1], a_l[mi], b_h + 2);
                }
            }
        }
        __syncthreads();
    }

    #pragma unroll
    for (int mi = 0; mi < 2; ++mi) {
        int r = row0 + wm * 32 + mi * 16 + (lane >> 2);
        #pragma unroll
        for (int nj = 0; nj < 8; ++nj) {
            int c = col0 + wn * 64 + nj * 8 + (lane & 3) * 2;
            float2 b2 = *reinterpret_cast<const float2*>(bias + c);
            float2 o0, o1;
            o0.x = acc[mi][nj][0] + b2.x;
            o0.y = acc[mi][nj][1] + b2.y;
            o1.x = acc[mi][nj][2] + b2.x;
            o1.y = acc[mi][nj][3] + b2.y;
            *reinterpret_cast<float2*>(C + (size_t)r * N + c)       = o0;
            *reinterpret_cast<float2*>(C + (size_t)(r + 8) * N + c) = o1;
        }
    }
}

// ---------------------------------------------------------------------------
// RMSNorm with fused hi/lo split output
// ---------------------------------------------------------------------------
__global__ void rmsnorm_split(const float* __restrict__ in, const float* __restrict__ g,
                              __nv_bfloat16* __restrict__ oh, __nv_bfloat16* __restrict__ ol,
                              int ncols, int in_stride) {
    const int row = blockIdx.x;
    const float* x = in + (size_t)row * in_stride;
    float ss = 0.f;
    for (int c = threadIdx.x; c < ncols; c += blockDim.x) {
        float v = x[c];
        ss += v * v;
    }
    __shared__ float red[32];
    #pragma unroll
    for (int o = 16; o > 0; o >>= 1) ss += __shfl_xor_sync(0xffffffff, ss, o);
    if ((threadIdx.x & 31) == 0) red[threadIdx.x >> 5] = ss;
    __syncthreads();
    __shared__ float s_scale;
    if (threadIdx.x == 0) {
        float t = 0.f;
        int nw = blockDim.x >> 5;
        for (int i = 0; i < nw; ++i) t += red[i];
        s_scale = 1.0f / sqrtf(t / (float)ncols + 1e-20f);
    }
    __syncthreads();
    const float sc = s_scale;
    size_t base = (size_t)row * ncols;
    for (int c = threadIdx.x; c < ncols; c += blockDim.x)
        split_store(oh, ol, base + c, x[c] * sc * g[c]);
}

// ---------------------------------------------------------------------------
// RoPE + assembles -> bf16 hi/lo
// ---------------------------------------------------------------------------
__device__ __forceinline__ float rope_angle(int s, int fi) {
    return (float)s * powf(10000.0f, -(float)(2 * fi) / 64.0f);
}

__global__ void assemble_q() {
    size_t idx = (size_t)blockIdx.x * blockDim.x + threadIdx.x;
    constexpr size_t total = (size_t)B_ * H_ * S_ * DH_;
    if (idx >= total) return;
    int d = (int)(idx % DH_);
    int s = (int)((idx / DH_) % S_);
    int h = (int)((idx / ((size_t)DH_ * S_)) % H_);
    int b = (int)(idx / ((size_t)DH_ * S_ * H_));
    const float* row = g_qb + ((size_t)(b * S_ + s)) * (H_ * DH_) + h * DH_;
    float val;
    if (d >= DR_) {
        val = row[d - DR_];
    } else {
        int fi = d & 31;
        float x   = row[DN_ + d];
        float rot = (d < 32) ? -row[DN_ + d + 32] : row[DN_ + d - 32];
        float ang = rope_angle(s, fi);
        val = x * cosf(ang) + rot * sinf(ang);
    }
    split_store(g_Qh, g_Ql, idx, val);
}

__global__ void assemble_k() {
    size_t idx = (size_t)blockIdx.x * blockDim.x + threadIdx.x;
    constexpr size_t total = (size_t)B_ * HKV_ * S_ * DH_;
    if (idx >= total) return;
    int d  = (int)(idx % DH_);
    int s  = (int)((idx / DH_) % S_);
    int hk = (int)((idx / ((size_t)DH_ * S_)) % HKV_);
    int b  = (int)(idx / ((size_t)DH_ * S_ * HKV_));
    float val;
    if (d >= DR_) {
        val = g_kvb[(size_t)(b * S_ + s) * (HKV_ * (DN_ + DV_)) + hk * (DN_ + DV_) + (d - DR_)];
    } else {
        int fi = d & 31;
        const float* kr = g_kva + (size_t)(b * S_ + s) * KVA_NPAD + RKV_;
        float x   = kr[d];
        float rot = (d < 32) ? -kr[d + 32] : kr[d - 32];
        float ang = rope_angle(s, fi);
        val = x * cosf(ang) + rot * sinf(ang);
    }
    split_store(g_Kh, g_Kl, idx, val);
}

__global__ void assemble_v() {
    size_t idx = (size_t)blockIdx.x * blockDim.x + threadIdx.x;
    constexpr size_t total = (size_t)B_ * HKV_ * DV_ * S_;
    if (idx >= total) return;
    int s  = (int)(idx % S_);
    int d  = (int)((idx / S_) % DV_);
    int hk = (int)((idx / ((size_t)S_ * DV_)) % HKV_);
    int b  = (int)(idx / ((size_t)S_ * DV_ * HKV_));
    float v = g_kvb[(size_t)(b * S_ + s) * (HKV_ * (DN_ + DV_)) + hk * (DN_ + DV_) + DN_ + d];
    split_store(g_Vth, g_Vtl, idx, v);
}

// ---------------------------------------------------------------------------
// Flash attention on mma.sync bf16 hi/lo (epilogue emits hi/lo split).
// ---------------------------------------------------------------------------
constexpr int FA_QSTR = 200;
constexpr int FA_VSTR = 72;
constexpr int FA_SMEM = (2 * 128 * FA_QSTR + 2 * 64 * FA_QSTR + 2 * 128 * FA_VSTR) * 2;

__global__ void __launch_bounds__(256, 1)
flash_mma() {
    extern __shared__ __align__(16) uint16_t fs[];
    uint16_t* Qh = fs;
    uint16_t* Ql = Qh + 128 * FA_QSTR;
    uint16_t* Kh = Ql + 128 * FA_QSTR;
    uint16_t* Kl = Kh + 64 * FA_QSTR;
    uint16_t* Vh = Kl + 64 * FA_QSTR;
    uint16_t* Vl = Vh + 128 * FA_VSTR;

    const int bh = blockIdx.x;
    const int b  = bh / H_;
    const int h  = bh % H_;
    const int hkv = h / G_;
    const int qb = (int)gridDim.y - 1 - (int)blockIdx.y;
    const int q0 = qb * 128;

    const int tid  = threadIdx.x;
    const int lane = tid & 31;
    const int wid  = tid >> 5;

    const __nv_bfloat16* Qhg = g_Qh + ((size_t)(b * H_ + h) * S_) * DH_;
    const __nv_bfloat16* Qlg = g_Ql + ((size_t)(b * H_ + h) * S_) * DH_;
    const __nv_bfloat16* Khg = g_Kh + ((size_t)(b * HKV_ + hkv) * S_) * DH_;
    const __nv_bfloat16* Klg = g_Kl + ((size_t)(b * HKV_ + hkv) * S_) * DH_;
    const __nv_bfloat16* Vhg = g_Vth + ((size_t)(b * HKV_ + hkv) * DV_) * S_;
    const __nv_bfloat16* Vlg = g_Vtl + ((size_t)(b * HKV_ + hkv) * DV_) * S_;

    {
        int r = tid >> 1, half = tid & 1;
        #pragma unroll
        for (int i = 0; i < 12; ++i) {
            int q = half * 12 + i;
            *reinterpret_cast<uint4*>(Qh + r * FA_QSTR + q * 8) =
                *reinterpret_cast<const uint4*>(Qhg + (size_t)(q0 + r) * DH_ + q * 8);
            *reinterpret_cast<uint4*>(Ql + r * FA_QSTR + q * 8) =
                *reinterpret_cast<const uint4*>(Qlg + (size_t)(q0 + r) * DH_ + q * 8);
        }
    }

    const int a_row = ((lane >> 3) & 1) * 8 + (lane & 7);
    const int a_kof = (lane >> 4) * 8;
    const int b_row = (lane >> 4) * 8 + (lane & 7);
    const int b_kof = ((lane >> 3) & 1) * 8;
    const int rl = lane >> 2, cb = (lane & 3) * 2;
    const int rg0 = q0 + wid * 16 + rl;
    const float scale = rsqrtf((float)DH_);

    float accO[8][2][4];
    #pragma unroll
    for (int i = 0; i < 8; ++i)
        #pragma unroll
        for (int j = 0; j < 2; ++j)
            #pragma unroll
            for (int q = 0; q < 4; ++q) accO[i][j][q] = 0.f;
    float m0 = -1e30f, m1 = -1e30f, l0 = 0.f, l1 = 0.f;

    const int T = 2 * (qb + 1);
    for (int t = 0; t < T; ++t) {
        const int j0 = t * 64;
        __syncthreads();
        {
            int r = tid >> 2, part = tid & 3;
            #pragma unroll
            for (int i = 0; i < 6; ++i) {
                int q = part * 6 + i;
                *reinterpret_cast<uint4*>(Kh + r * FA_QSTR + q * 8) =
                    *reinterpret_cast<const uint4*>(Khg + (size_t)(j0 + r) * DH_ + q * 8);
                *reinterpret_cast<uint4*>(Kl + r * FA_QSTR + q * 8) =
                    *reinterpret_cast<const uint4*>(Klg + (size_t)(j0 + r) * DH_ + q * 8);
            }
        }
        {
            int r = tid >> 1, part = tid & 1;
            #pragma unroll
            for (int i = 0; i < 4; ++i) {
                int q = part * 4 + i;
                *reinterpret_cast<uint4*>(Vh + r * FA_VSTR + q * 8) =
                    *reinterpret_cast<const uint4*>(Vhg + (size_t)r * S_ + j0 + q * 8);
                *reinterpret_cast<uint4*>(Vl + r * FA_VSTR + q * 8) =
                    *reinterpret_cast<const uint4*>(Vlg + (size_t)r * S_ + j0 + q * 8);
            }
        }
        __syncthreads();

        float Sc[4][2][4];
        #pragma unroll
        for (int i = 0; i < 4; ++i)
            #pragma unroll
            for (int j = 0; j < 2; ++j)
                #pragma unroll
                for (int q = 0; q < 4; ++q) Sc[i][j][q] = 0.f;

        #pragma unroll
        for (int ks = 0; ks < 12; ++ks) {
            uint32_t ah[4], al[4];
            uint32_t qoff = (uint32_t)((wid * 16 + a_row) * FA_QSTR + ks * 16 + a_kof) * 2;
            ldm_x4(ah, smem_u32(Qh) + qoff);
            ldm_x4(al, smem_u32(Ql) + qoff);
            #pragma unroll
            for (int nb = 0; nb < 4; ++nb) {
                uint32_t koff = (uint32_t)((nb * 16 + b_row) * FA_QSTR + ks * 16 + b_kof) * 2;
                uint32_t bh4[4], bl4[4];
                ldm_x4(bh4, smem_u32(Kh) + koff);
                ldm_x4(bl4, smem_u32(Kl) + koff);
                mma_bf16(Sc[nb][0], ah, bh4 + 0);
                mma_bf16(Sc[nb][1], ah, bh4 + 2);
                mma_bf16(Sc[nb][0], ah, bl4 + 0);
                mma_bf16(Sc[nb][1], ah, bl4 + 2);
                mma_bf16(Sc[nb][0], al, bh4 + 0);
                mma_bf16(Sc[nb][1], al, bh4 + 2);
            }
        }

        const bool domask = (j0 + 63) > (q0 + wid * 16);
        #pragma unroll
        for (int nb = 0; nb < 4; ++nb)
            #pragma unroll
            for (int mm = 0; mm < 2; ++mm) {
                int c = j0 + nb * 16 + mm * 8 + cb;
                float* s4 = Sc[nb][mm];
                s4[0] *= scale; s4[1] *= scale; s4[2] *= scale; s4[3] *= scale;
                if (domask) {
                    if (c     > rg0)     s4[0] = -1e30f;
                    if (c + 1 > rg0)     s4[1] = -1e30f;
                    if (c     > rg0 + 8) s4[2] = -1e30f;
                    if (c + 1 > rg0 + 8) s4[3] = -1e30f;
                }
            }

        float mx0 = -1e30f, mx1 = -1e30f;
        #pragma unroll
        for (int nb = 0; nb < 4; ++nb)
            #pragma unroll
            for (int mm = 0; mm < 2; ++mm) {
                mx0 = fmaxf(mx0, fmaxf(Sc[nb][mm][0], Sc[nb][mm][1]));
                mx1 = fmaxf(mx1, fmaxf(Sc[nb][mm][2], Sc[nb][mm][3]));
            }
        mx0 = fmaxf(mx0, __shfl_xor_sync(0xffffffff, mx0, 1));
        mx0 = fmaxf(mx0, __shfl_xor_sync(0xffffffff, mx0, 2));
        mx1 = fmaxf(mx1, __shfl_xor_sync(0xffffffff, mx1, 1));
        mx1 = fmaxf(mx1, __shfl_xor_sync(0xffffffff, mx1, 2));
        float mn0 = fmaxf(m0, mx0), mn1 = fmaxf(m1, mx1);
        float corr0 = __expf(m0 - mn0), corr1 = __expf(m1 - mn1);
        m0 = mn0; m1 = mn1;

        uint32_t aPh[4][4], aPl[4][4];
        float sum0 = 0.f, sum1 = 0.f;
        #pragma unroll
        for (int nb = 0; nb < 4; ++nb) {
            float e00, e01, e02, e03, e10, e11, e12, e13;
            e00 = __expf(Sc[nb][0][0] - mn0);  e01 = __expf(Sc[nb][0][1] - mn0);
            e02 = __expf(Sc[nb][0][2] - mn1);  e03 = __expf(Sc[nb][0][3] - mn1);
            e10 = __expf(Sc[nb][1][0] - mn0);  e11 = __expf(Sc[nb][1][1] - mn0);
            e12 = __expf(Sc[nb][1][2] - mn1);  e13 = __expf(Sc[nb][1][3] - mn1);
            sum0 += e00 + e01 + e10 + e11;
            sum1 += e02 + e03 + e12 + e13;
            aPh[nb][0] = pack_hi2(e00, e01);  aPl[nb][0] = pack_lo2(e00, e01);
            aPh[nb][1] = pack_hi2(e02, e03);  aPl[nb][1] = pack_lo2(e02, e03);
            aPh[nb][2] = pack_hi2(e10, e11);  aPl[nb][2] = pack_lo2(e10, e11);
            aPh[nb][3] = pack_hi2(e12, e13);  aPl[nb][3] = pack_lo2(e12, e13);
        }
        sum0 += __shfl_xor_sync(0xffffffff, sum0, 1);
        sum0 += __shfl_xor_sync(0xffffffff, sum0, 2);
        sum1 += __shfl_xor_sync(0xffffffff, sum1, 1);
        sum1 += __shfl_xor_sync(0xffffffff, sum1, 2);
        l0 = l0 * corr0 + sum0;
        l1 = l1 * corr1 + sum1;

        #pragma unroll
        for (int nv = 0; nv < 8; ++nv)
            #pragma unroll
            for (int mm = 0; mm < 2; ++mm) {
                accO[nv][mm][0] *= corr0; accO[nv][mm][1] *= corr0;
                accO[nv][mm][2] *= corr1; accO[nv][mm][3] *= corr1;
            }

        #pragma unroll
        for (int ks = 0; ks < 4; ++ks) {
            #pragma unroll
            for (int nv = 0; nv < 8; ++nv) {
                uint32_t voff = (uint32_t)((nv * 16 + b_row) * FA_VSTR + ks * 16 + b_kof) * 2;
                uint32_t bh4[4], bl4[4];
                ldm_x4(bh4, smem_u32(Vh) + voff);
                ldm_x4(bl4, smem_u32(Vl) + voff);
                mma_bf16(accO[nv][0], aPh[ks], bh4 + 0);
                mma_bf16(accO[nv][1], aPh[ks], bh4 + 2);
                mma_bf16(accO[nv][0], aPh[ks], bl4 + 0);
                mma_bf16(accO[nv][1], aPh[ks], bl4 + 2);
                mma_bf16(accO[nv][0], aPl[ks], bh4 + 0);
                mma_bf16(accO[nv][1], aPl[ks], bh4 + 2);
            }
        }
    }

    // ---- epilogue: normalize + hi/lo split store ----
    const float il0 = 1.0f / l0, il1 = 1.0f / l1;
    #pragma unroll
    for (int nv = 0; nv < 8; ++nv)
        #pragma unroll
        for (int mm = 0; mm < 2; ++mm) {
            int c = nv * 16 + mm * 8 + cb;
            size_t base0 = ((size_t)(b * S_) + rg0)     * (H_ * DV_) + h * DV_ + c;
            size_t base1 = ((size_t)(b * S_) + rg0 + 8) * (H_ * DV_) + h * DV_ + c;
            float x0 = accO[nv][mm][0] * il0, y0 = accO[nv][mm][1] * il0;
            float x1 = accO[nv][mm][2] * il1, y1 = accO[nv][mm][3] * il1;
            *reinterpret_cast<uint32_t*>(g_atth + base0) = pack_hi2(x0, y0);
            *reinterpret_cast<uint32_t*>(g_attl + base0) = pack_lo2(x0, y0);
            *reinterpret_cast<uint32_t*>(g_atth + base1) = pack_hi2(x1, y1);
            *reinterpret_cast<uint32_t*>(g_attl + base1) = pack_lo2(x1, y1);
        }
}

// ---------------------------------------------------------------------------
// Launch sequence
// ---------------------------------------------------------------------------
extern "C" void kernel_launch(void* const* d_in, const int* in_sizes, int n_in,
                              void* d_out, int out_size) {
    const float* hs    = (const float*)d_in[0];
    const float* w_qa  = (const float*)d_in[2];
    const float* b_qa  = (const float*)d_in[3];
    const float* gq    = (const float*)d_in[4];
    const float* w_qb  = (const float*)d_in[5];
    const float* b_qb  = (const float*)d_in[6];
    const float* w_kva = (const float*)d_in[7];
    const float* b_kva = (const float*)d_in[8];
    const float* gkv   = (const float*)d_in[9];
    const float* w_kvb = (const float*)d_in[10];
    const float* b_kvb = (const float*)d_in[11];
    const float* w_o   = (const float*)d_in[12];
    const float* b_o   = (const float*)d_in[13];
    float* out = (float*)d_out;

    float *p_qa, *p_qb, *p_kva, *p_kvb, *p_bkva;
    cudaGetSymbolAddress((void**)&p_qa,   g_qa);
    cudaGetSymbolAddress((void**)&p_qb,   g_qb);
    cudaGetSymbolAddress((void**)&p_kva,  g_kva);
    cudaGetSymbolAddress((void**)&p_kvb,  g_kvb);
    cudaGetSymbolAddress((void**)&p_bkva, g_bkva);
    __nv_bfloat16 *qa_h, *qa_l, *qb_h, *qb_l, *kva_h, *kva_l, *kvb_h, *kvb_l, *o_h, *o_l;
    cudaGetSymbolAddress((void**)&qa_h,  g_wqa_h);  cudaGetSymbolAddress((void**)&qa_l,  g_wqa_l);
    cudaGetSymbolAddress((void**)&qb_h,  g_wqb_h);  cudaGetSymbolAddress((void**)&qb_l,  g_wqb_l);
    cudaGetSymbolAddress((void**)&kva_h, g_wkva_h); cudaGetSymbolAddress((void**)&kva_l, g_wkva_l);
    cudaGetSymbolAddress((void**)&kvb_h, g_wkvb_h); cudaGetSymbolAddress((void**)&kvb_l, g_wkvb_l);
    cudaGetSymbolAddress((void**)&o_h,   g_wo_h);   cudaGetSymbolAddress((void**)&o_l,   g_wo_l);
    __nv_bfloat16 *hs_h, *hs_l, *qn_h, *qn_l, *kvn_h, *kvn_l, *att_h, *att_l;
    cudaGetSymbolAddress((void**)&hs_h,  g_hsh);  cudaGetSymbolAddress((void**)&hs_l,  g_hsl);
    cudaGetSymbolAddress((void**)&qn_h,  g_qnh);  cudaGetSymbolAddress((void**)&qn_l,  g_qnl);
    cudaGetSymbolAddress((void**)&kvn_h, g_kvnh); cudaGetSymbolAddress((void**)&kvn_l, g_kvnl);
    cudaGetSymbolAddress((void**)&att_h, g_atth); cudaGetSymbolAddress((void**)&att_l, g_attl);

    cudaFuncSetAttribute(flash_mma, cudaFuncAttributeMaxDynamicSharedMemorySize, FA_SMEM);
    cudaFuncSetAttribute(gemm_mma2, cudaFuncAttributeMaxDynamicSharedMemorySize, GEMM_SMEM2);

    // ---- weight prep + activation split ----
    dim3 tb(32, 8);
    prep_w<<<dim3(D_ / 32,  RQ_ / 32),           tb>>>(w_qa,  qa_h,  qa_l,  D_,  RQ_,       RQ_);
    prep_w<<<dim3(RQ_ / 32, (H_ * DH_) / 32),    tb>>>(w_qb,  qb_h,  qb_l,  RQ_, H_ * DH_,  H_ * DH_);
    prep_w<<<dim3(D_ / 32,  KVA_NPAD / 32),      tb>>>(w_kva, kva_h, kva_l, D_,  KVA_N,     KVA_NPAD);
    prep_w<<<dim3(RKV_ / 32, (HKV_ * 256) / 32), tb>>>(w_kvb, kvb_h, kvb_l, RKV_, HKV_ * 256, HKV_ * 256);
    prep_w<<<dim3(D_ / 32,  D_ / 32),            tb>>>(w_o,   o_h,   o_l,   D_,  D_,        D_);
    pad_bias_kva<<<(KVA_NPAD + 255) / 256, 256>>>(b_kva);
    {
        constexpr size_t th = (size_t)M_ * D_;
        split_act<<<(unsigned)((th + 255) / 256), 256>>>(hs, hs_h, hs_l, th);
    }

    // ---- projections (cp.async double-buffered HMMA) ----
    gemm_mma2<<<dim3(RQ_ / 128, M_ / 128), 256, GEMM_SMEM2>>>(hs_h, hs_l, qa_h, qa_l, b_qa, p_qa, M_, RQ_, D_);
    rmsnorm_split<<<M_, 256>>>(p_qa, gq, qn_h, qn_l, RQ_, RQ_);
    gemm_mma2<<<dim3((H_ * DH_) / 128, M_ / 128), 256, GEMM_SMEM2>>>(qn_h, qn_l, qb_h, qb_l, b_qb, p_qb, M_, H_ * DH_, RQ_);
    gemm_mma2<<<dim3(KVA_NPAD / 128, M_ / 128), 256, GEMM_SMEM2>>>(hs_h, hs_l, kva_h, kva_l, p_bkva, p_kva, M_, KVA_NPAD, D_);
    rmsnorm_split<<<M_, 256>>>(p_kva, gkv, kvn_h, kvn_l, RKV_, KVA_NPAD);
    gemm_mma2<<<dim3((HKV_ * 256) / 128, M_ / 128), 256, GEMM_SMEM2>>>(kvn_h, kvn_l, kvb_h, kvb_l, b_kvb, p_kvb, M_, HKV_ * 256, RKV_);

    // ---- assemble Q/K/V (bf16 hi/lo; V transposed) ----
    {
        constexpr size_t tq = (size_t)B_ * H_ * S_ * DH_;
        assemble_q<<<(unsigned)((tq + 255) / 256), 256>>>();
        constexpr size_t tk = (size_t)B_ * HKV_ * S_ * DH_;
        assemble_k<<<(unsigned)((tk + 255) / 256), 256>>>();
        constexpr size_t tv = (size_t)B_ * HKV_ * DV_ * S_;
        assemble_v<<<(unsigned)((tv + 255) / 256), 256>>>();
    }

    // ---- attention (tensor-core flash, hi/lo epilogue) ----
    flash_mma<<<dim3(B_ * H_, S_ / 128), 256, FA_SMEM>>>();

    // ---- output projection ----
    gemm_mma2<<<dim3(D_ / 128, M_ / 128), 256, GEMM_SMEM2>>>(att_h, att_l, o_h, o_l, b_o, out, M_, D_, D_);
}

// round 7
// speedup vs baseline: 3.0864x; 1.0342x over previous
#include <cuda_runtime.h>
#include <cuda_bf16.h>
#include <cstdint>
#include <math.h>

// ---------------------------------------------------------------------------
// Problem constants
// ---------------------------------------------------------------------------
namespace {
constexpr int B_   = 2;
constexpr int S_   = 2048;
constexpr int D_   = 2048;
constexpr int H_   = 16;
constexpr int HKV_ = 4;
constexpr int G_   = H_ / HKV_;
constexpr int RQ_  = 1024;
constexpr int RKV_ = 512;
constexpr int DH_  = 192;
constexpr int DR_  = 64;
constexpr int DN_  = 128;
constexpr int DV_  = 128;
constexpr int M_   = B_ * S_;          // 4096
constexpr int KVA_N    = RKV_ + DR_;   // 576
constexpr int KVA_NPAD = 640;
}

// ---------------------------------------------------------------------------
// Scratch (static device globals)
// ---------------------------------------------------------------------------
__device__ float g_qa  [(size_t)M_ * RQ_];
__device__ float g_qb  [(size_t)M_ * H_ * DH_];
__device__ float g_kva [(size_t)M_ * KVA_NPAD];
__device__ float g_kvb [(size_t)M_ * HKV_ * (DN_ + DV_)];
__device__ float g_bkva[KVA_NPAD];
__device__ float g_ct  [S_ * 32];
__device__ float g_st  [S_ * 32];

// pre-split activations (bf16 hi/lo)
__device__ __nv_bfloat16 g_hsh [(size_t)M_ * D_];
__device__ __nv_bfloat16 g_hsl [(size_t)M_ * D_];
__device__ __nv_bfloat16 g_qnh [(size_t)M_ * RQ_];
__device__ __nv_bfloat16 g_qnl [(size_t)M_ * RQ_];
__device__ __nv_bfloat16 g_kvnh[(size_t)M_ * RKV_];
__device__ __nv_bfloat16 g_kvnl[(size_t)M_ * RKV_];
__device__ __nv_bfloat16 g_atth[(size_t)M_ * H_ * DV_];
__device__ __nv_bfloat16 g_attl[(size_t)M_ * H_ * DV_];

// bf16 hi/lo Q/K ([b,h/hkv,s,d]) and V transposed ([b,hkv,d,s])
__device__ __nv_bfloat16 g_Qh [(size_t)B_ * H_   * S_ * DH_];
__device__ __nv_bfloat16 g_Ql [(size_t)B_ * H_   * S_ * DH_];
__device__ __nv_bfloat16 g_Kh [(size_t)B_ * HKV_ * S_ * DH_];
__device__ __nv_bfloat16 g_Kl [(size_t)B_ * HKV_ * S_ * DH_];
__device__ __nv_bfloat16 g_Vth[(size_t)B_ * HKV_ * DV_ * S_];
__device__ __nv_bfloat16 g_Vtl[(size_t)B_ * HKV_ * DV_ * S_];

// Pre-split / transposed weights: [N, K] bf16, hi + lo
__device__ __nv_bfloat16 g_wqa_h [(size_t)RQ_ * D_];
__device__ __nv_bfloat16 g_wqa_l [(size_t)RQ_ * D_];
__device__ __nv_bfloat16 g_wqb_h [(size_t)(H_ * DH_) * RQ_];
__device__ __nv_bfloat16 g_wqb_l [(size_t)(H_ * DH_) * RQ_];
__device__ __nv_bfloat16 g_wkva_h[(size_t)KVA_NPAD * D_];
__device__ __nv_bfloat16 g_wkva_l[(size_t)KVA_NPAD * D_];
__device__ __nv_bfloat16 g_wkvb_h[(size_t)(HKV_ * (DN_ + DV_)) * RKV_];
__device__ __nv_bfloat16 g_wkvb_l[(size_t)(HKV_ * (DN_ + DV_)) * RKV_];
__device__ __nv_bfloat16 g_wo_h  [(size_t)D_ * D_];
__device__ __nv_bfloat16 g_wo_l  [(size_t)D_ * D_];

// ---------------------------------------------------------------------------
// mma.sync / cp.async helpers
// ---------------------------------------------------------------------------
__device__ __forceinline__ uint32_t smem_u32(const void* p) {
    return (uint32_t)__cvta_generic_to_shared(p);
}
__device__ __forceinline__ void ldm_x4(uint32_t* r, uint32_t addr) {
    asm volatile("ldmatrix.sync.aligned.m8n8.x4.shared.b16 {%0,%1,%2,%3}, [%4];"
                 : "=r"(r[0]), "=r"(r[1]), "=r"(r[2]), "=r"(r[3]) : "r"(addr));
}
__device__ __forceinline__ void mma_bf16(float* c, const uint32_t* a, const uint32_t* b) {
    asm volatile("mma.sync.aligned.m16n8k16.row.col.f32.bf16.bf16.f32 "
                 "{%0,%1,%2,%3}, {%4,%5,%6,%7}, {%8,%9}, {%0,%1,%2,%3};"
                 : "+f"(c[0]), "+f"(c[1]), "+f"(c[2]), "+f"(c[3])
                 : "r"(a[0]), "r"(a[1]), "r"(a[2]), "r"(a[3]), "r"(b[0]), "r"(b[1]));
}
__device__ __forceinline__ void cp16(uint32_t dst, const void* src) {
    asm volatile("cp.async.cg.shared.global [%0], [%1], 16;"
                 :: "r"(dst), "l"(__cvta_generic_to_global(src)));
}
__device__ __forceinline__ void cp_commit() {
    asm volatile("cp.async.commit_group;");
}
template <int N_> __device__ __forceinline__ void cp_wait() {
    asm volatile("cp.async.wait_group %0;" :: "n"(N_));
}
__device__ __forceinline__ uint32_t pack_bf2(__nv_bfloat16 a, __nv_bfloat16 b) {
    return (uint32_t)__bfloat16_as_ushort(a) | ((uint32_t)__bfloat16_as_ushort(b) << 16);
}
__device__ __forceinline__ uint32_t pack_hi2(float x, float y) {
    return pack_bf2(__float2bfloat16(x), __float2bfloat16(y));
}
__device__ __forceinline__ uint32_t pack_lo2(float x, float y) {
    __nv_bfloat16 hx = __float2bfloat16(x), hy = __float2bfloat16(y);
    return pack_bf2(__float2bfloat16(x - __bfloat162float(hx)),
                    __float2bfloat16(y - __bfloat162float(hy)));
}
__device__ __forceinline__ void split_store(__nv_bfloat16* Hh, __nv_bfloat16* Ll,
                                            size_t idx, float v) {
    __nv_bfloat16 h = __float2bfloat16(v);
    Hh[idx] = h;
    Ll[idx] = __float2bfloat16(v - __bfloat162float(h));
}

// ---------------------------------------------------------------------------
// Prep kernels
// ---------------------------------------------------------------------------
__global__ void prep_w(const float* __restrict__ W, __nv_bfloat16* __restrict__ Hh,
                       __nv_bfloat16* __restrict__ Ll, int K, int N, int Npad) {
    __shared__ float t[32][33];
    const int kb = blockIdx.x * 32, nb = blockIdx.y * 32;
    const int tx = threadIdx.x, ty = threadIdx.y;
    #pragma unroll
    for (int i = 0; i < 4; ++i) {
        int k = kb + ty + i * 8;
        int n = nb + tx;
        t[ty + i * 8][tx] = (n < N) ? W[(size_t)k * N + n] : 0.f;
    }
    __syncthreads();
    #pragma unroll
    for (int i = 0; i < 4; ++i) {
        int n = nb + ty + i * 8;
        if (n >= Npad) continue;
        int k = kb + tx;
        split_store(Hh, Ll, (size_t)n * K + k, t[tx][ty + i * 8]);
    }
}

__global__ void pad_bias_kva(const float* __restrict__ b) {
    int i = threadIdx.x + blockIdx.x * blockDim.x;
    if (i < KVA_NPAD) g_bkva[i] = (i < KVA_N) ? b[i] : 0.f;
}

// RoPE table (bit-identical math to reference path)
__global__ void rope_table() {
    int i = blockIdx.x * blockDim.x + threadIdx.x;
    if (i >= S_ * 32) return;
    int s = i >> 5, fi = i & 31;
    float ang = (float)s * powf(10000.0f, -(float)(2 * fi) / 64.0f);
    g_ct[i] = cosf(ang);
    g_st[i] = sinf(ang);
}

// fp32 -> bf16 hi/lo split, float4-vectorized
__global__ void split_act4(const float4* __restrict__ X, uint2* __restrict__ Hh,
                           uint2* __restrict__ Ll, size_t n4) {
    size_t i = (size_t)blockIdx.x * blockDim.x + threadIdx.x;
    if (i >= n4) return;
    float4 v = X[i];
    Hh[i] = make_uint2(pack_hi2(v.x, v.y), pack_hi2(v.z, v.w));
    Ll[i] = make_uint2(pack_lo2(v.x, v.y), pack_lo2(v.z, v.w));
}

// ---------------------------------------------------------------------------
// HMMA GEMM, cp.async double-buffered, ONE sync per k-chunk.
// C[M,N] = (Ah+Al)[M,K] @ (Bh+Bl)[N,K]^T + bias   (3-product hi/lo, fp32 acc)
// ---------------------------------------------------------------------------
constexpr int ASTRIDE = 40;                       // uint16 per smem row (80B)
constexpr int GARR    = 128 * ASTRIDE;            // uint16 per array
constexpr int GEMM_SMEM2 = 2 * 4 * GARR * 2;      // 2 stages x 4 arrays, bytes

__global__ void __launch_bounds__(256)
gemm_mma2(const __nv_bfloat16* __restrict__ Agh, const __nv_bfloat16* __restrict__ Agl,
          const __nv_bfloat16* __restrict__ Bgh, const __nv_bfloat16* __restrict__ Bgl,
          const float* __restrict__ bias, float* __restrict__ C,
          int M, int N, int K) {
    extern __shared__ __align__(16) uint16_t gs[];
    const int tid  = threadIdx.x;
    const int lane = tid & 31;
    const int wid  = tid >> 5;
    const int wm   = wid & 3;
    const int wn   = wid >> 2;
    const int row0 = blockIdx.y * 128, col0 = blockIdx.x * 128;
    const uint32_t sb = smem_u32(gs);

    float acc[2][8][4];
    #pragma unroll
    for (int i = 0; i < 2; ++i)
        #pragma unroll
        for (int j = 0; j < 8; ++j)
            #pragma unroll
            for (int q = 0; q < 4; ++q) acc[i][j][q] = 0.f;

    const int a_row = ((lane >> 3) & 1) * 8 + (lane & 7);
    const int a_kof = (lane >> 4) * 8;
    const int b_row = (lane >> 4) * 8 + (lane & 7);
    const int b_kof = ((lane >> 3) & 1) * 8;

    const int nch = K >> 5;

    auto prefetch = [&](int c) {
        const int k0 = c << 5;
        const int s = c & 1;
        #pragma unroll
        for (int it = 0; it < 8; ++it) {
            int idx = tid + it * 256;
            int arr = idx >> 9;                 // 0 Ah, 1 Al, 2 Bh, 3 Bl
            int j   = idx & 511;
            int r   = j >> 2, q = j & 3;
            const __nv_bfloat16* src = (arr == 0) ? Agh : (arr == 1) ? Agl
                                     : (arr == 2) ? Bgh : Bgl;
            size_t goff = (size_t)(((arr < 2) ? row0 : col0) + r) * K + k0 + q * 8;
            uint32_t dst = sb + (uint32_t)(((s * 4 + arr) * 128 + r) * ASTRIDE + q * 8) * 2;
            cp16(dst, src + goff);
        }
        cp_commit();
    };

    prefetch(0);
    for (int c = 0; c < nch; ++c) {
        cp_wait<0>();
        __syncthreads();
        // Safe: all warps completed mma(c-1) (reader of stage (c+1)&1) at the
        // barrier above; concurrent mma(c) reads stage c&1 only.
        if (c + 1 < nch) prefetch(c + 1);

        const uint32_t base = sb + (uint32_t)((c & 1) * 4 * GARR) * 2;
        const uint32_t sAh = base;
        const uint32_t sAl = base + (uint32_t)GARR * 2;
        const uint32_t sBh = base + (uint32_t)GARR * 4;
        const uint32_t sBl = base + (uint32_t)GARR * 6;

        #pragma unroll
        for (int ks = 0; ks < 2; ++ks) {
            const int ke = ks * 16;
            uint32_t a_h[2][4], a_l[2][4];
            #pragma unroll
            for (int mi = 0; mi < 2; ++mi) {
                int r = wm * 32 + mi * 16 + a_row;
                uint32_t off = (uint32_t)(r * ASTRIDE + ke + a_kof) * 2;
                ldm_x4(a_h[mi], sAh + off);
                ldm_x4(a_l[mi], sAl + off);
            }
            #pragma unroll
            for (int nb = 0; nb < 4; ++nb) {
                int n = wn * 64 + nb * 16 + b_row;
                uint32_t off = (uint32_t)(n * ASTRIDE + ke + b_kof) * 2;
                uint32_t b_h[4], b_l[4];
                ldm_x4(b_h, sBh + off);
                ldm_x4(b_l, sBl + off);
                #pragma unroll
                for (int mi = 0; mi < 2; ++mi) {
                    mma_bf16(acc[mi][nb * 2 + 0], a_h[mi], b_h + 0);
                    mma_bf16(acc[mi][nb * 2 + 1], a_h[mi], b_h + 2);
                    mma_bf16(acc[mi][nb * 2 + 0], a_h[mi], b_l + 0);
                    mma_bf16(acc[mi][nb * 2 + 1], a_h[mi], b_l + 2);
                    mma_bf16(acc[mi][nb * 2 + 0], a_l[mi], b_h + 0);
                    mma_bf16(acc[mi][nb * 2 + 1], a_l[mi], b_h + 2);
                }
            }
        }
    }

    #pragma unroll
    for (int mi = 0; mi < 2; ++mi) {
        int r = row0 + wm * 32 + mi * 16 + (lane >> 2);
        #pragma unroll
        for (int nj = 0; nj < 8; ++nj) {
            int c = col0 + wn * 64 + nj * 8 + (lane & 3) * 2;
            float2 b2 = *reinterpret_cast<const float2*>(bias + c);
            float2 o0, o1;
            o0.x = acc[mi][nj][0] + b2.x;
            o0.y = acc[mi][nj][1] + b2.y;
            o1.x = acc[mi][nj][2] + b2.x;
            o1.y = acc[mi][nj][3] + b2.y;
            *reinterpret_cast<float2*>(C + (size_t)r * N + c)       = o0;
            *reinterpret_cast<float2*>(C + (size_t)(r + 8) * N + c) = o1;
        }
    }
}

// ---------------------------------------------------------------------------
// RMSNorm with fused hi/lo split output
// ---------------------------------------------------------------------------
__global__ void rmsnorm_split(const float* __restrict__ in, const float* __restrict__ g,
                              __nv_bfloat16* __restrict__ oh, __nv_bfloat16* __restrict__ ol,
                              int ncols, int in_stride) {
    const int row = blockIdx.x;
    const float* x = in + (size_t)row * in_stride;
    float ss = 0.f;
    for (int c = threadIdx.x; c < ncols; c += blockDim.x) {
        float v = x[c];
        ss += v * v;
    }
    __shared__ float red[32];
    #pragma unroll
    for (int o = 16; o > 0; o >>= 1) ss += __shfl_xor_sync(0xffffffff, ss, o);
    if ((threadIdx.x & 31) == 0) red[threadIdx.x >> 5] = ss;
    __syncthreads();
    __shared__ float s_scale;
    if (threadIdx.x == 0) {
        float t = 0.f;
        int nw = blockDim.x >> 5;
        for (int i = 0; i < nw; ++i) t += red[i];
        s_scale = 1.0f / sqrtf(t / (float)ncols + 1e-20f);
    }
    __syncthreads();
    const float sc = s_scale;
    size_t base = (size_t)row * ncols;
    for (int c = threadIdx.x; c < ncols; c += blockDim.x)
        split_store(oh, ol, base + c, x[c] * sc * g[c]);
}

// ---------------------------------------------------------------------------
// Assembles (table-based RoPE) -> bf16 hi/lo
// ---------------------------------------------------------------------------
__global__ void assemble_q() {
    size_t idx = (size_t)blockIdx.x * blockDim.x + threadIdx.x;
    constexpr size_t total = (size_t)B_ * H_ * S_ * DH_;
    if (idx >= total) return;
    int d = (int)(idx % DH_);
    int s = (int)((idx / DH_) % S_);
    int h = (int)((idx / ((size_t)DH_ * S_)) % H_);
    int b = (int)(idx / ((size_t)DH_ * S_ * H_));
    const float* row = g_qb + ((size_t)(b * S_ + s)) * (H_ * DH_) + h * DH_;
    float val;
    if (d >= DR_) {
        val = row[d - DR_];
    } else {
        int fi = d & 31;
        float x   = row[DN_ + d];
        float rot = (d < 32) ? -row[DN_ + d + 32] : row[DN_ + d - 32];
        val = x * g_ct[s * 32 + fi] + rot * g_st[s * 32 + fi];
    }
    split_store(g_Qh, g_Ql, idx, val);
}

__global__ void assemble_k() {
    size_t idx = (size_t)blockIdx.x * blockDim.x + threadIdx.x;
    constexpr size_t total = (size_t)B_ * HKV_ * S_ * DH_;
    if (idx >= total) return;
    int d  = (int)(idx % DH_);
    int s  = (int)((idx / DH_) % S_);
    int hk = (int)((idx / ((size_t)DH_ * S_)) % HKV_);
    int b  = (int)(idx / ((size_t)DH_ * S_ * HKV_));
    float val;
    if (d >= DR_) {
        val = g_kvb[(size_t)(b * S_ + s) * (HKV_ * (DN_ + DV_)) + hk * (DN_ + DV_) + (d - DR_)];
    } else {
        int fi = d & 31;
        const float* kr = g_kva + (size_t)(b * S_ + s) * KVA_NPAD + RKV_;
        float x   = kr[d];
        float rot = (d < 32) ? -kr[d + 32] : kr[d - 32];
        val = x * g_ct[s * 32 + fi] + rot * g_st[s * 32 + fi];
    }
    split_store(g_Kh, g_Kl, idx, val);
}

__global__ void assemble_v() {
    size_t idx = (size_t)blockIdx.x * blockDim.x + threadIdx.x;
    constexpr size_t total = (size_t)B_ * HKV_ * DV_ * S_;
    if (idx >= total) return;
    int s  = (int)(idx % S_);
    int d  = (int)((idx / S_) % DV_);
    int hk = (int)((idx / ((size_t)S_ * DV_)) % HKV_);
    int b  = (int)(idx / ((size_t)S_ * DV_ * HKV_));
    float v = g_kvb[(size_t)(b * S_ + s) * (HKV_ * (DN_ + DV_)) + hk * (DN_ + DV_) + DN_ + d];
    split_store(g_Vth, g_Vtl, idx, v);
}

// ---------------------------------------------------------------------------
// Flash attention on mma.sync bf16 hi/lo (epilogue emits hi/lo split).
// ---------------------------------------------------------------------------
constexpr int FA_QSTR = 200;
constexpr int FA_VSTR = 72;
constexpr int FA_SMEM = (2 * 128 * FA_QSTR + 2 * 64 * FA_QSTR + 2 * 128 * FA_VSTR) * 2;

__global__ void __launch_bounds__(256, 1)
flash_mma() {
    extern __shared__ __align__(16) uint16_t fs[];
    uint16_t* Qh = fs;
    uint16_t* Ql = Qh + 128 * FA_QSTR;
    uint16_t* Kh = Ql + 128 * FA_QSTR;
    uint16_t* Kl = Kh + 64 * FA_QSTR;
    uint16_t* Vh = Kl + 64 * FA_QSTR;
    uint16_t* Vl = Vh + 128 * FA_VSTR;

    const int bh = blockIdx.x;
    const int b  = bh / H_;
    const int h  = bh % H_;
    const int hkv = h / G_;
    const int qb = (int)gridDim.y - 1 - (int)blockIdx.y;
    const int q0 = qb * 128;

    const int tid  = threadIdx.x;
    const int lane = tid & 31;
    const int wid  = tid >> 5;

    const __nv_bfloat16* Qhg = g_Qh + ((size_t)(b * H_ + h) * S_) * DH_;
    const __nv_bfloat16* Qlg = g_Ql + ((size_t)(b * H_ + h) * S_) * DH_;
    const __nv_bfloat16* Khg = g_Kh + ((size_t)(b * HKV_ + hkv) * S_) * DH_;
    const __nv_bfloat16* Klg = g_Kl + ((size_t)(b * HKV_ + hkv) * S_) * DH_;
    const __nv_bfloat16* Vhg = g_Vth + ((size_t)(b * HKV_ + hkv) * DV_) * S_;
    const __nv_bfloat16* Vlg = g_Vtl + ((size_t)(b * HKV_ + hkv) * DV_) * S_;

    {
        int r = tid >> 1, half = tid & 1;
        #pragma unroll
        for (int i = 0; i < 12; ++i) {
            int q = half * 12 + i;
            *reinterpret_cast<uint4*>(Qh + r * FA_QSTR + q * 8) =
                *reinterpret_cast<const uint4*>(Qhg + (size_t)(q0 + r) * DH_ + q * 8);
            *reinterpret_cast<uint4*>(Ql + r * FA_QSTR + q * 8) =
                *reinterpret_cast<const uint4*>(Qlg + (size_t)(q0 + r) * DH_ + q * 8);
        }
    }

    const int a_row = ((lane >> 3) & 1) * 8 + (lane & 7);
    const int a_kof = (lane >> 4) * 8;
    const int b_row = (lane >> 4) * 8 + (lane & 7);
    const int b_kof = ((lane >> 3) & 1) * 8;
    const int rl = lane >> 2, cb = (lane & 3) * 2;
    const int rg0 = q0 + wid * 16 + rl;
    const float scale = rsqrtf((float)DH_);

    float accO[8][2][4];
    #pragma unroll
    for (int i = 0; i < 8; ++i)
        #pragma unroll
        for (int j = 0; j < 2; ++j)
            #pragma unroll
            for (int q = 0; q < 4; ++q) accO[i][j][q] = 0.f;
    float m0 = -1e30f, m1 = -1e30f, l0 = 0.f, l1 = 0.f;

    const int T = 2 * (qb + 1);
    for (int t = 0; t < T; ++t) {
        const int j0 = t * 64;
        __syncthreads();
        {
            int r = tid >> 2, part = tid & 3;
            #pragma unroll
            for (int i = 0; i < 6; ++i) {
                int q = part * 6 + i;
                *reinterpret_cast<uint4*>(Kh + r * FA_QSTR + q * 8) =
                    *reinterpret_cast<const uint4*>(Khg + (size_t)(j0 + r) * DH_ + q * 8);
                *reinterpret_cast<uint4*>(Kl + r * FA_QSTR + q * 8) =
                    *reinterpret_cast<const uint4*>(Klg + (size_t)(j0 + r) * DH_ + q * 8);
            }
        }
        {
            int r = tid >> 1, part = tid & 1;
            #pragma unroll
            for (int i = 0; i < 4; ++i) {
                int q = part * 4 + i;
                *reinterpret_cast<uint4*>(Vh + r * FA_VSTR + q * 8) =
                    *reinterpret_cast<const uint4*>(Vhg + (size_t)r * S_ + j0 + q * 8);
                *reinterpret_cast<uint4*>(Vl + r * FA_VSTR + q * 8) =
                    *reinterpret_cast<const uint4*>(Vlg + (size_t)r * S_ + j0 + q * 8);
            }
        }
        __syncthreads();

        float Sc[4][2][4];
        #pragma unroll
        for (int i = 0; i < 4; ++i)
            #pragma unroll
            for (int j = 0; j < 2; ++j)
                #pragma unroll
                for (int q = 0; q < 4; ++q) Sc[i][j][q] = 0.f;

        #pragma unroll
        for (int ks = 0; ks < 12; ++ks) {
            uint32_t ah[4], al[4];
            uint32_t qoff = (uint32_t)((wid * 16 + a_row) * FA_QSTR + ks * 16 + a_kof) * 2;
            ldm_x4(ah, smem_u32(Qh) + qoff);
            ldm_x4(al, smem_u32(Ql) + qoff);
            #pragma unroll
            for (int nb = 0; nb < 4; ++nb) {
                uint32_t koff = (uint32_t)((nb * 16 + b_row) * FA_QSTR + ks * 16 + b_kof) * 2;
                uint32_t bh4[4], bl4[4];
                ldm_x4(bh4, smem_u32(Kh) + koff);
                ldm_x4(bl4, smem_u32(Kl) + koff);
                mma_bf16(Sc[nb][0], ah, bh4 + 0);
                mma_bf16(Sc[nb][1], ah, bh4 + 2);
                mma_bf16(Sc[nb][0], ah, bl4 + 0);
                mma_bf16(Sc[nb][1], ah, bl4 + 2);
                mma_bf16(Sc[nb][0], al, bh4 + 0);
                mma_bf16(Sc[nb][1], al, bh4 + 2);
            }
        }

        const bool domask = (j0 + 63) > (q0 + wid * 16);
        #pragma unroll
        for (int nb = 0; nb < 4; ++nb)
            #pragma unroll
            for (int mm = 0; mm < 2; ++mm) {
                int c = j0 + nb * 16 + mm * 8 + cb;
                float* s4 = Sc[nb][mm];
                s4[0] *= scale; s4[1] *= scale; s4[2] *= scale; s4[3] *= scale;
                if (domask) {
                    if (c     > rg0)     s4[0] = -1e30f;
                    if (c + 1 > rg0)     s4[1] = -1e30f;
                    if (c     > rg0 + 8) s4[2] = -1e30f;
                    if (c + 1 > rg0 + 8) s4[3] = -1e30f;
                }
            }

        float mx0 = -1e30f, mx1 = -1e30f;
        #pragma unroll
        for (int nb = 0; nb < 4; ++nb)
            #pragma unroll
            for (int mm = 0; mm < 2; ++mm) {
                mx0 = fmaxf(mx0, fmaxf(Sc[nb][mm][0], Sc[nb][mm][1]));
                mx1 = fmaxf(mx1, fmaxf(Sc[nb][mm][2], Sc[nb][mm][3]));
            }
        mx0 = fmaxf(mx0, __shfl_xor_sync(0xffffffff, mx0, 1));
        mx0 = fmaxf(mx0, __shfl_xor_sync(0xffffffff, mx0, 2));
        mx1 = fmaxf(mx1, __shfl_xor_sync(0xffffffff, mx1, 1));
        mx1 = fmaxf(mx1, __shfl_xor_sync(0xffffffff, mx1, 2));
        float mn0 = fmaxf(m0, mx0), mn1 = fmaxf(m1, mx1);
        float corr0 = __expf(m0 - mn0), corr1 = __expf(m1 - mn1);
        m0 = mn0; m1 = mn1;

        uint32_t aPh[4][4], aPl[4][4];
        float sum0 = 0.f, sum1 = 0.f;
        #pragma unroll
        for (int nb = 0; nb < 4; ++nb) {
            float e00, e01, e02, e03, e10, e11, e12, e13;
            e00 = __expf(Sc[nb][0][0] - mn0);  e01 = __expf(Sc[nb][0][1] - mn0);
            e02 = __expf(Sc[nb][0][2] - mn1);  e03 = __expf(Sc[nb][0][3] - mn1);
            e10 = __expf(Sc[nb][1][0] - mn0);  e11 = __expf(Sc[nb][1][1] - mn0);
            e12 = __expf(Sc[nb][1][2] - mn1);  e13 = __expf(Sc[nb][1][3] - mn1);
            sum0 += e00 + e01 + e10 + e11;
            sum1 += e02 + e03 + e12 + e13;
            aPh[nb][0] = pack_hi2(e00, e01);  aPl[nb][0] = pack_lo2(e00, e01);
            aPh[nb][1] = pack_hi2(e02, e03);  aPl[nb][1] = pack_lo2(e02, e03);
            aPh[nb][2] = pack_hi2(e10, e11);  aPl[nb][2] = pack_lo2(e10, e11);
            aPh[nb][3] = pack_hi2(e12, e13);  aPl[nb][3] = pack_lo2(e12, e13);
        }
        sum0 += __shfl_xor_sync(0xffffffff, sum0, 1);
        sum0 += __shfl_xor_sync(0xffffffff, sum0, 2);
        sum1 += __shfl_xor_sync(0xffffffff, sum1, 1);
        sum1 += __shfl_xor_sync(0xffffffff, sum1, 2);
        l0 = l0 * corr0 + sum0;
        l1 = l1 * corr1 + sum1;

        #pragma unroll
        for (int nv = 0; nv < 8; ++nv)
            #pragma unroll
            for (int mm = 0; mm < 2; ++mm) {
                accO[nv][mm][0] *= corr0; accO[nv][mm][1] *= corr0;
                accO[nv][mm][2] *= corr1; accO[nv][mm][3] *= corr1;
            }

        #pragma unroll
        for (int ks = 0; ks < 4; ++ks) {
            #pragma unroll
            for (int nv = 0; nv < 8; ++nv) {
                uint32_t voff = (uint32_t)((nv * 16 + b_row) * FA_VSTR + ks * 16 + b_kof) * 2;
                uint32_t bh4[4], bl4[4];
                ldm_x4(bh4, smem_u32(Vh) + voff);
                ldm_x4(bl4, smem_u32(Vl) + voff);
                mma_bf16(accO[nv][0], aPh[ks], bh4 + 0);
                mma_bf16(accO[nv][1], aPh[ks], bh4 + 2);
                mma_bf16(accO[nv][0], aPh[ks], bl4 + 0);
                mma_bf16(accO[nv][1], aPh[ks], bl4 + 2);
                mma_bf16(accO[nv][0], aPl[ks], bh4 + 0);
                mma_bf16(accO[nv][1], aPl[ks], bh4 + 2);
            }
        }
    }

    const float il0 = 1.0f / l0, il1 = 1.0f / l1;
    #pragma unroll
    for (int nv = 0; nv < 8; ++nv)
        #pragma unroll
        for (int mm = 0; mm < 2; ++mm) {
            int c = nv * 16 + mm * 8 + cb;
            size_t base0 = ((size_t)(b * S_) + rg0)     * (H_ * DV_) + h * DV_ + c;
            size_t base1 = ((size_t)(b * S_) + rg0 + 8) * (H_ * DV_) + h * DV_ + c;
            float x0 = accO[nv][mm][0] * il0, y0 = accO[nv][mm][1] * il0;
            float x1 = accO[nv][mm][2] * il1, y1 = accO[nv][mm][3] * il1;
            *reinterpret_cast<uint32_t*>(g_atth + base0) = pack_hi2(x0, y0);
            *reinterpret_cast<uint32_t*>(g_attl + base0) = pack_lo2(x0, y0);
            *reinterpret_cast<uint32_t*>(g_atth + base1) = pack_hi2(x1, y1);
            *reinterpret_cast<uint32_t*>(g_attl + base1) = pack_lo2(x1, y1);
        }
}

// ---------------------------------------------------------------------------
// Launch sequence
// ---------------------------------------------------------------------------
extern "C" void kernel_launch(void* const* d_in, const int* in_sizes, int n_in,
                              void* d_out, int out_size) {
    const float* hs    = (const float*)d_in[0];
    const float* w_qa  = (const float*)d_in[2];
    const float* b_qa  = (const float*)d_in[3];
    const float* gq    = (const float*)d_in[4];
    const float* w_qb  = (const float*)d_in[5];
    const float* b_qb  = (const float*)d_in[6];
    const float* w_kva = (const float*)d_in[7];
    const float* b_kva = (const float*)d_in[8];
    const float* gkv   = (const float*)d_in[9];
    const float* w_kvb = (const float*)d_in[10];
    const float* b_kvb = (const float*)d_in[11];
    const float* w_o   = (const float*)d_in[12];
    const float* b_o   = (const float*)d_in[13];
    float* out = (float*)d_out;

    float *p_qa, *p_qb, *p_kva, *p_kvb, *p_bkva;
    cudaGetSymbolAddress((void**)&p_qa,   g_qa);
    cudaGetSymbolAddress((void**)&p_qb,   g_qb);
    cudaGetSymbolAddress((void**)&p_kva,  g_kva);
    cudaGetSymbolAddress((void**)&p_kvb,  g_kvb);
    cudaGetSymbolAddress((void**)&p_bkva, g_bkva);
    __nv_bfloat16 *qa_h, *qa_l, *qb_h, *qb_l, *kva_h, *kva_l, *kvb_h, *kvb_l, *o_h, *o_l;
    cudaGetSymbolAddress((void**)&qa_h,  g_wqa_h);  cudaGetSymbolAddress((void**)&qa_l,  g_wqa_l);
    cudaGetSymbolAddress((void**)&qb_h,  g_wqb_h);  cudaGetSymbolAddress((void**)&qb_l,  g_wqb_l);
    cudaGetSymbolAddress((void**)&kva_h, g_wkva_h); cudaGetSymbolAddress((void**)&kva_l, g_wkva_l);
    cudaGetSymbolAddress((void**)&kvb_h, g_wkvb_h); cudaGetSymbolAddress((void**)&kvb_l, g_wkvb_l);
    cudaGetSymbolAddress((void**)&o_h,   g_wo_h);   cudaGetSymbolAddress((void**)&o_l,   g_wo_l);
    __nv_bfloat16 *hs_h, *hs_l, *qn_h, *qn_l, *kvn_h, *kvn_l, *att_h, *att_l;
    cudaGetSymbolAddress((void**)&hs_h,  g_hsh);  cudaGetSymbolAddress((void**)&hs_l,  g_hsl);
    cudaGetSymbolAddress((void**)&qn_h,  g_qnh);  cudaGetSymbolAddress((void**)&qn_l,  g_qnl);
    cudaGetSymbolAddress((void**)&kvn_h, g_kvnh); cudaGetSymbolAddress((void**)&kvn_l, g_kvnl);
    cudaGetSymbolAddress((void**)&att_h, g_atth); cudaGetSymbolAddress((void**)&att_l, g_attl);

    cudaFuncSetAttribute(flash_mma, cudaFuncAttributeMaxDynamicSharedMemorySize, FA_SMEM);
    cudaFuncSetAttribute(gemm_mma2, cudaFuncAttributeMaxDynamicSharedMemorySize, GEMM_SMEM2);

    // ---- prep: weights, bias pad, rope table, hs split ----
    dim3 tb(32, 8);
    prep_w<<<dim3(D_ / 32,  RQ_ / 32),           tb>>>(w_qa,  qa_h,  qa_l,  D_,  RQ_,       RQ_);
    prep_w<<<dim3(RQ_ / 32, (H_ * DH_) / 32),    tb>>>(w_qb,  qb_h,  qb_l,  RQ_, H_ * DH_,  H_ * DH_);
    prep_w<<<dim3(D_ / 32,  KVA_NPAD / 32),      tb>>>(w_kva, kva_h, kva_l, D_,  KVA_N,     KVA_NPAD);
    prep_w<<<dim3(RKV_ / 32, (HKV_ * 256) / 32), tb>>>(w_kvb, kvb_h, kvb_l, RKV_, HKV_ * 256, HKV_ * 256);
    prep_w<<<dim3(D_ / 32,  D_ / 32),            tb>>>(w_o,   o_h,   o_l,   D_,  D_,        D_);
    pad_bias_kva<<<(KVA_NPAD + 255) / 256, 256>>>(b_kva);
    rope_table<<<(S_ * 32 + 255) / 256, 256>>>();
    {
        constexpr size_t n4 = (size_t)M_ * D_ / 4;
        split_act4<<<(unsigned)((n4 + 255) / 256), 256>>>(
            (const float4*)hs, (uint2*)hs_h, (uint2*)hs_l, n4);
    }

    // ---- projections (cp.async double-buffered HMMA, 1 sync/chunk) ----
    gemm_mma2<<<dim3(RQ_ / 128, M_ / 128), 256, GEMM_SMEM2>>>(hs_h, hs_l, qa_h, qa_l, b_qa, p_qa, M_, RQ_, D_);
    rmsnorm_split<<<M_, 256>>>(p_qa, gq, qn_h, qn_l, RQ_, RQ_);
    gemm_mma2<<<dim3((H_ * DH_) / 128, M_ / 128), 256, GEMM_SMEM2>>>(qn_h, qn_l, qb_h, qb_l, b_qb, p_qb, M_, H_ * DH_, RQ_);
    gemm_mma2<<<dim3(KVA_NPAD / 128, M_ / 128), 256, GEMM_SMEM2>>>(hs_h, hs_l, kva_h, kva_l, p_bkva, p_kva, M_, KVA_NPAD, D_);
    rmsnorm_split<<<M_, 256>>>(p_kva, gkv, kvn_h, kvn_l, RKV_, KVA_NPAD);
    gemm_mma2<<<dim3((HKV_ * 256) / 128, M_ / 128), 256, GEMM_SMEM2>>>(kvn_h, kvn_l, kvb_h, kvb_l, b_kvb, p_kvb, M_, HKV_ * 256, RKV_);

    // ---- assemble Q/K/V (table RoPE; bf16 hi/lo; V transposed) ----
    {
        constexpr size_t tq = (size_t)B_ * H_ * S_ * DH_;
        assemble_q<<<(unsigned)((tq + 255) / 256), 256>>>();
        constexpr size_t tk = (size_t)B_ * HKV_ * S_ * DH_;
        assemble_k<<<(unsigned)((tk + 255) / 256), 256>>>();
        constexpr size_t tv = (size_t)B_ * HKV_ * DV_ * S_;
        assemble_v<<<(unsigned)((tv + 255) / 256), 256>>>();
    }

    // ---- attention (tensor-core flash, hi/lo epilogue) ----
    flash_mma<<<dim3(B_ * H_, S_ / 128), 256, FA_SMEM>>>();

    // ---- output projection ----
    gemm_mma2<<<dim3(D_ / 128, M_ / 128), 256, GEMM_SMEM2>>>(att_h, att_l, o_h, o_l, b_o, out, M_, D_, D_);
}